// round 1
// baseline (speedup 1.0000x reference)
#include <cuda_runtime.h>
#include <math.h>

#define BSZ 2
#define SEQ 2048
#define EMB 768
#define NH 12
#define HDIM 64
#define ROWS (BSZ*SEQ)

// Scratch (allocation-free rule: __device__ globals)
__device__ float g_q1[BSZ*NH*SEQ*HDIM];
__device__ float g_k1[BSZ*NH*SEQ*HDIM];
__device__ float g_v1[BSZ*NH*SEQ*HDIM];
__device__ float g_q2[BSZ*NH*SEQ*HDIM];
__device__ float g_k2[BSZ*NH*SEQ*HDIM];
__device__ float g_att[ROWS*EMB];
__device__ float g_xn[ROWS*EMB];

// ---------------------------------------------------------------------------
// QKV projection GEMM: C = X[4096,768] @ W[768, ncols], scattering each column
// into [B,H,N,HD]-layout Q/K/V tensors.  which==0 -> (q1,k1,v1), which==1 -> (q2,k2)
// ---------------------------------------------------------------------------
__global__ void qkv_gemm_kernel(const float* __restrict__ X, const float* __restrict__ W,
                                int which)
{
    __shared__ float As[16][65];
    __shared__ float Bs[16][65];
    const int tid = threadIdx.x;
    const int tx = tid & 15, ty = tid >> 4;
    const int m0 = blockIdx.y * 64;
    const int n0 = blockIdx.x * 64;

    float acc[4][4] = {};
    for (int kk = 0; kk < EMB; kk += 16) {
        #pragma unroll
        for (int r = 0; r < 4; r++) {
            int idx = tid + r * 256;
            int mi = idx >> 4, ki = idx & 15;
            As[ki][mi] = X[(m0 + mi) * EMB + kk + ki];
            int bi = idx >> 6, nj = idx & 63;
            Bs[bi][nj] = W[(kk + bi) * 2304 + n0 + nj];
        }
        __syncthreads();
        #pragma unroll
        for (int k = 0; k < 16; k++) {
            float a[4], bv[4];
            #pragma unroll
            for (int i = 0; i < 4; i++) a[i] = As[k][ty * 4 + i];
            #pragma unroll
            for (int j = 0; j < 4; j++) bv[j] = Bs[k][tx * 4 + j];
            #pragma unroll
            for (int i = 0; i < 4; i++)
                #pragma unroll
                for (int j = 0; j < 4; j++)
                    acc[i][j] = fmaf(a[i], bv[j], acc[i][j]);
        }
        __syncthreads();
    }

    float* Qd = which ? g_q2 : g_q1;
    float* Kd = which ? g_k2 : g_k1;
    float* Vd = g_v1;
    #pragma unroll
    for (int i = 0; i < 4; i++) {
        int r = m0 + ty * 4 + i;
        int b = r >> 11, n = r & (SEQ - 1);
        #pragma unroll
        for (int j = 0; j < 4; j++) {
            int c = n0 + tx * 4 + j;
            int sel = c / EMB;
            int within = c - sel * EMB;
            int h = within >> 6, d = within & 63;
            long idx = (((long)(b * NH + h)) * SEQ + n) * HDIM + d;
            float* dst = (sel == 0) ? Qd : ((sel == 1) ? Kd : Vd);
            dst[idx] = acc[i][j];
        }
    }
}

// ---------------------------------------------------------------------------
// Fused differential flash attention: both softmaxes streamed together,
// out = softmax(Q1K1^T*s)@V1 - lam * softmax(Q2K2^T*s)@V1
// grid (SEQ/64, B*H), 256 threads, 64q x 64k tiles, 4x4 micro tiles.
// ---------------------------------------------------------------------------
__global__ void diff_attn_kernel(const float* __restrict__ lam1, const float* __restrict__ lam2)
{
    extern __shared__ float sm[];
    float* Q1s = sm;               // 64*65 each
    float* Q2s = Q1s + 64 * 65;
    float* K1s = Q2s + 64 * 65;
    float* K2s = K1s + 64 * 65;
    float* Vs  = K2s + 64 * 65;
    float* P1s = Vs  + 64 * 65;
    float* P2s = P1s + 64 * 65;

    const int tid = threadIdx.x;
    const int tx = tid & 15, ty = tid >> 4;
    const int bh = blockIdx.y;
    const int b = bh / NH, h = bh - b * NH;
    const int q0 = blockIdx.x * 64;
    const float scale = 0.125f;   // 64^-0.5

    const float* Q1g = g_q1 + (((long)bh) * SEQ + q0) * HDIM;
    const float* Q2g = g_q2 + (((long)bh) * SEQ + q0) * HDIM;
    const float* K1g = g_k1 + ((long)bh) * SEQ * HDIM;
    const float* K2g = g_k2 + ((long)bh) * SEQ * HDIM;
    const float* V1g = g_v1 + ((long)bh) * SEQ * HDIM;

    for (int idx = tid; idx < 64 * 64; idx += 256) {
        int qi = idx >> 6, d = idx & 63;
        Q1s[qi * 65 + d] = Q1g[qi * HDIM + d] * scale;
        Q2s[qi * 65 + d] = Q2g[qi * HDIM + d] * scale;
    }

    float m1[4], l1[4], m2[4], l2[4];
    float o1[4][4] = {}, o2[4][4] = {};
    #pragma unroll
    for (int i = 0; i < 4; i++) { m1[i] = -INFINITY; m2[i] = -INFINITY; l1[i] = 0.f; l2[i] = 0.f; }

    for (int kt = 0; kt < SEQ / 64; kt++) {
        __syncthreads();   // protect prev iter's P/V reads
        for (int idx = tid; idx < 64 * 64; idx += 256) {
            int ki = idx >> 6, d = idx & 63;
            K1s[ki * 65 + d] = K1g[(kt * 64 + ki) * HDIM + d];
            K2s[ki * 65 + d] = K2g[(kt * 64 + ki) * HDIM + d];
            Vs [ki * 65 + d] = V1g[(kt * 64 + ki) * HDIM + d];
        }
        __syncthreads();

        float s1[4][4] = {}, s2[4][4] = {};
        for (int d = 0; d < 64; d++) {
            float qa[4], qb[4], ka[4], kb[4];
            #pragma unroll
            for (int i = 0; i < 4; i++) {
                qa[i] = Q1s[(ty * 4 + i) * 65 + d];
                qb[i] = Q2s[(ty * 4 + i) * 65 + d];
            }
            #pragma unroll
            for (int j = 0; j < 4; j++) {
                ka[j] = K1s[(tx * 4 + j) * 65 + d];
                kb[j] = K2s[(tx * 4 + j) * 65 + d];
            }
            #pragma unroll
            for (int i = 0; i < 4; i++)
                #pragma unroll
                for (int j = 0; j < 4; j++) {
                    s1[i][j] = fmaf(qa[i], ka[j], s1[i][j]);
                    s2[i][j] = fmaf(qb[i], kb[j], s2[i][j]);
                }
        }

        // online softmax update for both attentions
        #pragma unroll
        for (int i = 0; i < 4; i++) {
            // attn 1
            {
                float tm = fmaxf(fmaxf(s1[i][0], s1[i][1]), fmaxf(s1[i][2], s1[i][3]));
                #pragma unroll
                for (int off = 8; off > 0; off >>= 1)
                    tm = fmaxf(tm, __shfl_xor_sync(0xffffffffu, tm, off));
                float nm = fmaxf(m1[i], tm);
                float corr = expf(m1[i] - nm);
                float rs = 0.f;
                #pragma unroll
                for (int j = 0; j < 4; j++) { float p = expf(s1[i][j] - nm); s1[i][j] = p; rs += p; }
                #pragma unroll
                for (int off = 8; off > 0; off >>= 1)
                    rs += __shfl_xor_sync(0xffffffffu, rs, off);
                l1[i] = l1[i] * corr + rs; m1[i] = nm;
                #pragma unroll
                for (int j = 0; j < 4; j++) o1[i][j] *= corr;
            }
            // attn 2
            {
                float tm = fmaxf(fmaxf(s2[i][0], s2[i][1]), fmaxf(s2[i][2], s2[i][3]));
                #pragma unroll
                for (int off = 8; off > 0; off >>= 1)
                    tm = fmaxf(tm, __shfl_xor_sync(0xffffffffu, tm, off));
                float nm = fmaxf(m2[i], tm);
                float corr = expf(m2[i] - nm);
                float rs = 0.f;
                #pragma unroll
                for (int j = 0; j < 4; j++) { float p = expf(s2[i][j] - nm); s2[i][j] = p; rs += p; }
                #pragma unroll
                for (int off = 8; off > 0; off >>= 1)
                    rs += __shfl_xor_sync(0xffffffffu, rs, off);
                l2[i] = l2[i] * corr + rs; m2[i] = nm;
                #pragma unroll
                for (int j = 0; j < 4; j++) o2[i][j] *= corr;
            }
            #pragma unroll
            for (int j = 0; j < 4; j++) {
                P1s[(ty * 4 + i) * 65 + tx * 4 + j] = s1[i][j];
                P2s[(ty * 4 + i) * 65 + tx * 4 + j] = s2[i][j];
            }
        }
        __syncthreads();

        // O += P @ V (both attentions share V1 tile)
        for (int k = 0; k < 64; k++) {
            float v[4], p1v[4], p2v[4];
            #pragma unroll
            for (int j = 0; j < 4; j++) v[j] = Vs[k * 65 + tx * 4 + j];
            #pragma unroll
            for (int i = 0; i < 4; i++) {
                p1v[i] = P1s[(ty * 4 + i) * 65 + k];
                p2v[i] = P2s[(ty * 4 + i) * 65 + k];
            }
            #pragma unroll
            for (int i = 0; i < 4; i++)
                #pragma unroll
                for (int j = 0; j < 4; j++) {
                    o1[i][j] = fmaf(p1v[i], v[j], o1[i][j]);
                    o2[i][j] = fmaf(p2v[i], v[j], o2[i][j]);
                }
        }
    }

    const float lam = lam1[h] - lam2[h] + 0.1f;
    #pragma unroll
    for (int i = 0; i < 4; i++) {
        int n = q0 + ty * 4 + i;
        float inv1 = 1.f / l1[i], inv2 = 1.f / l2[i];
        #pragma unroll
        for (int j = 0; j < 4; j++) {
            int c = h * HDIM + tx * 4 + j;
            g_att[((long)(b * SEQ + n)) * EMB + c] = o1[i][j] * inv1 - lam * (o2[i][j] * inv2);
        }
    }
}

// ---------------------------------------------------------------------------
// RMSNorm over last dim (768), fp32
// ---------------------------------------------------------------------------
__global__ void rmsnorm_kernel(const float* __restrict__ w)
{
    const int r = blockIdx.x;
    const int tid = threadIdx.x;
    __shared__ float red[256];
    float ss = 0.f;
    for (int c = tid; c < EMB; c += 256) { float v = g_att[(long)r * EMB + c]; ss += v * v; }
    red[tid] = ss;
    __syncthreads();
    for (int s = 128; s > 0; s >>= 1) {
        if (tid < s) red[tid] += red[tid + s];
        __syncthreads();
    }
    float rms = rsqrtf(red[0] * (1.0f / EMB) + 1e-6f);
    for (int c = tid; c < EMB; c += 256)
        g_xn[(long)r * EMB + c] = g_att[(long)r * EMB + c] * rms * w[c];
}

// ---------------------------------------------------------------------------
// Output projection: out = Xn[4096,768] @ Wp[768,768] + bias
// ---------------------------------------------------------------------------
__global__ void proj_gemm_kernel(const float* __restrict__ W, const float* __restrict__ bias,
                                 float* __restrict__ out)
{
    __shared__ float As[16][65];
    __shared__ float Bs[16][65];
    const int tid = threadIdx.x;
    const int tx = tid & 15, ty = tid >> 4;
    const int m0 = blockIdx.y * 64;
    const int n0 = blockIdx.x * 64;

    float acc[4][4] = {};
    for (int kk = 0; kk < EMB; kk += 16) {
        #pragma unroll
        for (int r = 0; r < 4; r++) {
            int idx = tid + r * 256;
            int mi = idx >> 4, ki = idx & 15;
            As[ki][mi] = g_xn[(long)(m0 + mi) * EMB + kk + ki];
            int bi = idx >> 6, nj = idx & 63;
            Bs[bi][nj] = W[(kk + bi) * EMB + n0 + nj];
        }
        __syncthreads();
        #pragma unroll
        for (int k = 0; k < 16; k++) {
            float a[4], bv[4];
            #pragma unroll
            for (int i = 0; i < 4; i++) a[i] = As[k][ty * 4 + i];
            #pragma unroll
            for (int j = 0; j < 4; j++) bv[j] = Bs[k][tx * 4 + j];
            #pragma unroll
            for (int i = 0; i < 4; i++)
                #pragma unroll
                for (int j = 0; j < 4; j++)
                    acc[i][j] = fmaf(a[i], bv[j], acc[i][j]);
        }
        __syncthreads();
    }

    #pragma unroll
    for (int i = 0; i < 4; i++) {
        int r = m0 + ty * 4 + i;
        #pragma unroll
        for (int j = 0; j < 4; j++) {
            int c = n0 + tx * 4 + j;
            out[(long)r * EMB + c] = acc[i][j] + bias[c];
        }
    }
}

extern "C" void kernel_launch(void* const* d_in, const int* in_sizes, int n_in,
                              void* d_out, int out_size)
{
    const float* x  = (const float*)d_in[0];
    const float* W1 = (const float*)d_in[1];
    const float* W2 = (const float*)d_in[2];
    const float* Wp = (const float*)d_in[3];
    const float* bp = (const float*)d_in[4];
    const float* nw = (const float*)d_in[5];
    const float* l1 = (const float*)d_in[6];
    const float* l2 = (const float*)d_in[7];
    // d_in[8] = xpos (int64) unused: attention is non-causal in the reference
    float* out = (float*)d_out;

    // QKV projections (v2 is dead in the reference -> only 1536 cols for W2)
    qkv_gemm_kernel<<<dim3(36, 64), 256>>>(x, W1, 0);
    qkv_gemm_kernel<<<dim3(24, 64), 256>>>(x, W2, 1);

    const size_t smem = 7 * 64 * 65 * sizeof(float);  // 116480 B
    cudaFuncSetAttribute(diff_attn_kernel, cudaFuncAttributeMaxDynamicSharedMemorySize, (int)smem);
    diff_attn_kernel<<<dim3(SEQ / 64, BSZ * NH), 256, smem>>>(l1, l2);

    rmsnorm_kernel<<<ROWS, 256>>>(nw);
    proj_gemm_kernel<<<dim3(EMB / 64, ROWS / 64), 256>>>(Wp, bp, out);
}

// round 2
// speedup vs baseline: 4.7177x; 4.7177x over previous
#include <cuda_runtime.h>
#include <math.h>
#include <stdint.h>

#define BSZ 2
#define SEQ 2048
#define EMB 768
#define NH 12
#define HDIM 64
#define ROWS (BSZ*SEQ)

// Scratch (allocation-free rule: __device__ globals)
__device__ float g_q1[BSZ*NH*SEQ*HDIM];
__device__ float g_k1[BSZ*NH*SEQ*HDIM];
__device__ float g_v1[BSZ*NH*SEQ*HDIM];
__device__ float g_q2[BSZ*NH*SEQ*HDIM];
__device__ float g_k2[BSZ*NH*SEQ*HDIM];
__device__ float g_att[ROWS*EMB];
__device__ float g_xn[ROWS*EMB];

// ---------------------------------------------------------------------------
// tf32 helpers
// ---------------------------------------------------------------------------
__device__ __forceinline__ uint32_t cvt_tf32(float x) {
    uint32_t u;
    asm("cvt.rna.tf32.f32 %0, %1;" : "=r"(u) : "f"(x));
    return u;
}

__device__ __forceinline__ void mma8(float* c, const uint32_t* a, const uint32_t* b) {
    asm volatile(
        "mma.sync.aligned.m16n8k8.row.col.f32.tf32.tf32.f32 "
        "{%0,%1,%2,%3},{%4,%5,%6,%7},{%8,%9},{%0,%1,%2,%3};"
        : "+f"(c[0]), "+f"(c[1]), "+f"(c[2]), "+f"(c[3])
        : "r"(a[0]), "r"(a[1]), "r"(a[2]), "r"(a[3]), "r"(b[0]), "r"(b[1]));
}

// ---------------------------------------------------------------------------
// QKV projection GEMM via tensor cores (tf32 mma):
// C[4096, ncols] = X[4096,768] @ W[768, ncols] (W row stride 2304)
// scatter into [B,H,N,HD] tensors. which==0 -> (q1,k1,v1); which==1 -> (q2,k2)
// block: 256 thr (8 warps), tile 128x128, warp tile 32x64.
// ---------------------------------------------------------------------------
__global__ __launch_bounds__(256) void qkv_mma_kernel(const float* __restrict__ X,
                                                      const float* __restrict__ W,
                                                      int which)
{
    __shared__ uint32_t As[128*36];   // [row][k] stride 36 (36%32=4 -> bank=lane)
    __shared__ uint32_t Bs[32*136];   // [k][n]  stride 136 (136%32=8)

    const int tid  = threadIdx.x;
    const int lane = tid & 31, warp = tid >> 5;
    const int g = lane >> 2, tig = lane & 3;
    const int wm = warp >> 1, wn = warp & 1;
    const int m0 = blockIdx.y * 128, n0 = blockIdx.x * 128;

    float acc[2][8][4] = {};

    for (int kk = 0; kk < EMB; kk += 32) {
        #pragma unroll
        for (int it = 0; it < 4; it++) {
            int i = tid + it * 256;
            int row = i >> 3, c4 = i & 7;
            float4 v = *(const float4*)(X + (size_t)(m0 + row) * EMB + kk + 4 * c4);
            uint32_t* d = &As[row * 36 + 4 * c4];
            d[0] = cvt_tf32(v.x); d[1] = cvt_tf32(v.y); d[2] = cvt_tf32(v.z); d[3] = cvt_tf32(v.w);
        }
        #pragma unroll
        for (int it = 0; it < 4; it++) {
            int i = tid + it * 256;
            int row = i >> 5, c4 = i & 31;
            float4 v = *(const float4*)(W + (size_t)(kk + row) * 2304 + n0 + 4 * c4);
            uint32_t* d = &Bs[row * 136 + 4 * c4];
            d[0] = cvt_tf32(v.x); d[1] = cvt_tf32(v.y); d[2] = cvt_tf32(v.z); d[3] = cvt_tf32(v.w);
        }
        __syncthreads();

        #pragma unroll
        for (int ks = 0; ks < 4; ks++) {
            uint32_t a[2][4], b[8][2];
            #pragma unroll
            for (int mt = 0; mt < 2; mt++) {
                int r = 32 * wm + 16 * mt;
                a[mt][0] = As[(r + g)     * 36 + 8 * ks + tig];
                a[mt][1] = As[(r + g + 8) * 36 + 8 * ks + tig];
                a[mt][2] = As[(r + g)     * 36 + 8 * ks + tig + 4];
                a[mt][3] = As[(r + g + 8) * 36 + 8 * ks + tig + 4];
            }
            #pragma unroll
            for (int t = 0; t < 8; t++) {
                b[t][0] = Bs[(8 * ks + tig)     * 136 + 64 * wn + 8 * t + g];
                b[t][1] = Bs[(8 * ks + tig + 4) * 136 + 64 * wn + 8 * t + g];
            }
            #pragma unroll
            for (int mt = 0; mt < 2; mt++)
                #pragma unroll
                for (int t = 0; t < 8; t++)
                    mma8(acc[mt][t], a[mt], b[t]);
        }
        __syncthreads();
    }

    // epilogue: scatter into Q/K/V ([B,H,N,HD])
    const int cbase = n0 + 64 * wn;          // multiple of 64 -> one (sel, head)
    const int sel = cbase / EMB;
    const int h = (cbase - sel * EMB) >> 6;
    float* dst = (which == 0) ? (sel == 0 ? g_q1 : (sel == 1 ? g_k1 : g_v1))
                              : (sel == 0 ? g_q2 : g_k2);
    #pragma unroll
    for (int mt = 0; mt < 2; mt++) {
        int r = m0 + 32 * wm + 16 * mt + g;
        int bb = r >> 11, n = r & (SEQ - 1);
        size_t base = ((size_t)(bb * NH + h) * SEQ);
        #pragma unroll
        for (int t = 0; t < 8; t++) {
            int d0 = 8 * t + 2 * tig;
            *(float2*)&dst[(base + n) * HDIM + d0]     = make_float2(acc[mt][t][0], acc[mt][t][1]);
            *(float2*)&dst[(base + n + 8) * HDIM + d0] = make_float2(acc[mt][t][2], acc[mt][t][3]);
        }
    }
}

// ---------------------------------------------------------------------------
// Differential flash attention with tf32 mma.
// block: 256 thr (8 warps), q-tile 128 (16 rows/warp), k-tile 64.
// ---------------------------------------------------------------------------
__device__ __forceinline__ void softmax_update(
    float s[8][4], float m[2], float l[2], float o[8][4],
    uint32_t* __restrict__ Ps, int warp, int g, int tig)
{
    #pragma unroll
    for (int rr = 0; rr < 2; rr++) {
        const int i0 = rr * 2, i1 = rr * 2 + 1;
        float tm = -1e30f;
        #pragma unroll
        for (int t = 0; t < 8; t++) tm = fmaxf(tm, fmaxf(s[t][i0], s[t][i1]));
        tm = fmaxf(tm, __shfl_xor_sync(0xffffffffu, tm, 1));
        tm = fmaxf(tm, __shfl_xor_sync(0xffffffffu, tm, 2));
        float nm = fmaxf(m[rr], tm);
        float corr = __expf(m[rr] - nm);
        float rs = 0.f;
        #pragma unroll
        for (int t = 0; t < 8; t++) {
            float p0 = __expf(s[t][i0] - nm);
            float p1 = __expf(s[t][i1] - nm);
            s[t][i0] = p0; s[t][i1] = p1;
            rs += p0 + p1;
        }
        rs += __shfl_xor_sync(0xffffffffu, rs, 1);
        rs += __shfl_xor_sync(0xffffffffu, rs, 2);
        l[rr] = l[rr] * corr + rs;
        m[rr] = nm;
        #pragma unroll
        for (int t = 0; t < 8; t++) { o[t][i0] *= corr; o[t][i1] *= corr; }
        const int row = 16 * warp + g + 8 * rr;
        #pragma unroll
        for (int t = 0; t < 8; t++) {
            uint2 pk = make_uint2(cvt_tf32(s[t][i0]), cvt_tf32(s[t][i1]));
            *(uint2*)&Ps[row * 68 + 8 * t + 2 * tig] = pk;
        }
    }
}

__global__ __launch_bounds__(256) void diff_attn_mma(const float* __restrict__ lam1,
                                                     const float* __restrict__ lam2)
{
    extern __shared__ uint32_t sm[];
    uint32_t* Q1s = sm;                  // 128x68
    uint32_t* Q2s = Q1s + 128 * 68;
    uint32_t* K1s = Q2s + 128 * 68;      // 64x68
    uint32_t* K2s = K1s + 64 * 68;
    uint32_t* Vs  = K2s + 64 * 68;       // 64x72
    uint32_t* P1s = Vs  + 64 * 72;       // 128x68
    uint32_t* P2s = P1s + 128 * 68;

    const int tid  = threadIdx.x;
    const int lane = tid & 31, warp = tid >> 5;
    const int g = lane >> 2, tig = lane & 3;
    const int bh = blockIdx.y;
    const int b = bh / NH, h = bh - b * NH;
    const int q0 = blockIdx.x * 128;

    const float* Q1g = g_q1 + ((size_t)bh * SEQ + q0) * HDIM;
    const float* Q2g = g_q2 + ((size_t)bh * SEQ + q0) * HDIM;
    const float* K1g = g_k1 + (size_t)bh * SEQ * HDIM;
    const float* K2g = g_k2 + (size_t)bh * SEQ * HDIM;
    const float* V1g = g_v1 + (size_t)bh * SEQ * HDIM;

    // Q fill (scale folded in): 128x64 per tensor
    #pragma unroll
    for (int it = 0; it < 8; it++) {
        int i = tid + it * 256;
        int row = i >> 4, c4 = i & 15;
        float4 v = *(const float4*)(Q1g + row * HDIM + 4 * c4);
        uint32_t* d = &Q1s[row * 68 + 4 * c4];
        d[0] = cvt_tf32(v.x * 0.125f); d[1] = cvt_tf32(v.y * 0.125f);
        d[2] = cvt_tf32(v.z * 0.125f); d[3] = cvt_tf32(v.w * 0.125f);
        float4 w = *(const float4*)(Q2g + row * HDIM + 4 * c4);
        uint32_t* e = &Q2s[row * 68 + 4 * c4];
        e[0] = cvt_tf32(w.x * 0.125f); e[1] = cvt_tf32(w.y * 0.125f);
        e[2] = cvt_tf32(w.z * 0.125f); e[3] = cvt_tf32(w.w * 0.125f);
    }

    float o1[8][4] = {}, o2[8][4] = {};
    float m1[2] = {-1e30f, -1e30f}, m2[2] = {-1e30f, -1e30f};
    float l1v[2] = {0.f, 0.f}, l2v[2] = {0.f, 0.f};

    for (int kt = 0; kt < SEQ / 64; kt++) {
        __syncthreads();
        #pragma unroll
        for (int it = 0; it < 4; it++) {
            int i = tid + it * 256;
            int row = i >> 4, c4 = i & 15;
            size_t goff = ((size_t)kt * 64 + row) * HDIM + 4 * c4;
            float4 a = *(const float4*)(K1g + goff);
            uint32_t* d1 = &K1s[row * 68 + 4 * c4];
            d1[0] = cvt_tf32(a.x); d1[1] = cvt_tf32(a.y); d1[2] = cvt_tf32(a.z); d1[3] = cvt_tf32(a.w);
            float4 c = *(const float4*)(K2g + goff);
            uint32_t* d2 = &K2s[row * 68 + 4 * c4];
            d2[0] = cvt_tf32(c.x); d2[1] = cvt_tf32(c.y); d2[2] = cvt_tf32(c.z); d2[3] = cvt_tf32(c.w);
            float4 v = *(const float4*)(V1g + goff);
            uint32_t* d3 = &Vs[row * 72 + 4 * c4];
            d3[0] = cvt_tf32(v.x); d3[1] = cvt_tf32(v.y); d3[2] = cvt_tf32(v.z); d3[3] = cvt_tf32(v.w);
        }
        __syncthreads();

        const int r = 16 * warp;

        // ---- attn1: S1 = Q1 K1^T ----
        {
            float s1[8][4] = {};
            #pragma unroll
            for (int ks = 0; ks < 8; ks++) {
                uint32_t aq[4];
                aq[0] = Q1s[(r + g)     * 68 + 8 * ks + tig];
                aq[1] = Q1s[(r + g + 8) * 68 + 8 * ks + tig];
                aq[2] = Q1s[(r + g)     * 68 + 8 * ks + tig + 4];
                aq[3] = Q1s[(r + g + 8) * 68 + 8 * ks + tig + 4];
                #pragma unroll
                for (int t = 0; t < 8; t++) {
                    uint32_t bk[2];
                    bk[0] = K1s[(8 * t + g) * 68 + 8 * ks + tig];
                    bk[1] = K1s[(8 * t + g) * 68 + 8 * ks + tig + 4];
                    mma8(s1[t], aq, bk);
                }
            }
            softmax_update(s1, m1, l1v, o1, P1s, warp, g, tig);
        }
        // ---- attn2: S2 = Q2 K2^T ----
        {
            float s2[8][4] = {};
            #pragma unroll
            for (int ks = 0; ks < 8; ks++) {
                uint32_t aq[4];
                aq[0] = Q2s[(r + g)     * 68 + 8 * ks + tig];
                aq[1] = Q2s[(r + g + 8) * 68 + 8 * ks + tig];
                aq[2] = Q2s[(r + g)     * 68 + 8 * ks + tig + 4];
                aq[3] = Q2s[(r + g + 8) * 68 + 8 * ks + tig + 4];
                #pragma unroll
                for (int t = 0; t < 8; t++) {
                    uint32_t bk[2];
                    bk[0] = K2s[(8 * t + g) * 68 + 8 * ks + tig];
                    bk[1] = K2s[(8 * t + g) * 68 + 8 * ks + tig + 4];
                    mma8(s2[t], aq, bk);
                }
            }
            softmax_update(s2, m2, l2v, o2, P2s, warp, g, tig);
        }
        __syncwarp();

        // ---- O += P @ V (V shared between attns) ----
        #pragma unroll
        for (int ks = 0; ks < 8; ks++) {
            uint32_t a1[4], a2[4];
            a1[0] = P1s[(r + g)     * 68 + 8 * ks + tig];
            a1[1] = P1s[(r + g + 8) * 68 + 8 * ks + tig];
            a1[2] = P1s[(r + g)     * 68 + 8 * ks + tig + 4];
            a1[3] = P1s[(r + g + 8) * 68 + 8 * ks + tig + 4];
            a2[0] = P2s[(r + g)     * 68 + 8 * ks + tig];
            a2[1] = P2s[(r + g + 8) * 68 + 8 * ks + tig];
            a2[2] = P2s[(r + g)     * 68 + 8 * ks + tig + 4];
            a2[3] = P2s[(r + g + 8) * 68 + 8 * ks + tig + 4];
            #pragma unroll
            for (int t = 0; t < 8; t++) {
                uint32_t bv[2];
                bv[0] = Vs[(8 * ks + tig)     * 72 + 8 * t + g];
                bv[1] = Vs[(8 * ks + tig + 4) * 72 + 8 * t + g];
                mma8(o1[t], a1, bv);
                mma8(o2[t], a2, bv);
            }
        }
    }

    // epilogue
    const float lam = lam1[h] - lam2[h] + 0.1f;
    const float i10 = 1.f / l1v[0], i11 = 1.f / l1v[1];
    const float i20 = 1.f / l2v[0], i21 = 1.f / l2v[1];
    const int n = q0 + 16 * warp + g;
    #pragma unroll
    for (int t = 0; t < 8; t++) {
        const int col = h * HDIM + 8 * t + 2 * tig;
        float2 r0 = make_float2(o1[t][0] * i10 - lam * o2[t][0] * i20,
                                o1[t][1] * i10 - lam * o2[t][1] * i20);
        float2 r1 = make_float2(o1[t][2] * i11 - lam * o2[t][2] * i21,
                                o1[t][3] * i11 - lam * o2[t][3] * i21);
        *(float2*)&g_att[((size_t)(b * SEQ + n)) * EMB + col]     = r0;
        *(float2*)&g_att[((size_t)(b * SEQ + n + 8)) * EMB + col] = r1;
    }
}

// ---------------------------------------------------------------------------
// RMSNorm over last dim (768), fp32
// ---------------------------------------------------------------------------
__global__ void rmsnorm_kernel(const float* __restrict__ w)
{
    const int r = blockIdx.x;
    const int tid = threadIdx.x;
    __shared__ float red[256];
    float ss = 0.f;
    for (int c = tid; c < EMB; c += 256) { float v = g_att[(size_t)r * EMB + c]; ss += v * v; }
    red[tid] = ss;
    __syncthreads();
    for (int s = 128; s > 0; s >>= 1) {
        if (tid < s) red[tid] += red[tid + s];
        __syncthreads();
    }
    float rms = rsqrtf(red[0] * (1.0f / EMB) + 1e-6f);
    for (int c = tid; c < EMB; c += 256)
        g_xn[(size_t)r * EMB + c] = g_att[(size_t)r * EMB + c] * rms * w[c];
}

// ---------------------------------------------------------------------------
// Output projection via tf32 mma: out = Xn[4096,768] @ Wp[768,768] + bias
// ---------------------------------------------------------------------------
__global__ __launch_bounds__(256) void proj_mma_kernel(const float* __restrict__ W,
                                                       const float* __restrict__ bias,
                                                       float* __restrict__ out)
{
    __shared__ uint32_t As[128*36];
    __shared__ uint32_t Bs[32*136];

    const int tid  = threadIdx.x;
    const int lane = tid & 31, warp = tid >> 5;
    const int g = lane >> 2, tig = lane & 3;
    const int wm = warp >> 1, wn = warp & 1;
    const int m0 = blockIdx.y * 128, n0 = blockIdx.x * 128;

    float acc[2][8][4] = {};

    for (int kk = 0; kk < EMB; kk += 32) {
        #pragma unroll
        for (int it = 0; it < 4; it++) {
            int i = tid + it * 256;
            int row = i >> 3, c4 = i & 7;
            float4 v = *(const float4*)(g_xn + (size_t)(m0 + row) * EMB + kk + 4 * c4);
            uint32_t* d = &As[row * 36 + 4 * c4];
            d[0] = cvt_tf32(v.x); d[1] = cvt_tf32(v.y); d[2] = cvt_tf32(v.z); d[3] = cvt_tf32(v.w);
        }
        #pragma unroll
        for (int it = 0; it < 4; it++) {
            int i = tid + it * 256;
            int row = i >> 5, c4 = i & 31;
            float4 v = *(const float4*)(W + (size_t)(kk + row) * EMB + n0 + 4 * c4);
            uint32_t* d = &Bs[row * 136 + 4 * c4];
            d[0] = cvt_tf32(v.x); d[1] = cvt_tf32(v.y); d[2] = cvt_tf32(v.z); d[3] = cvt_tf32(v.w);
        }
        __syncthreads();

        #pragma unroll
        for (int ks = 0; ks < 4; ks++) {
            uint32_t a[2][4], b[8][2];
            #pragma unroll
            for (int mt = 0; mt < 2; mt++) {
                int r = 32 * wm + 16 * mt;
                a[mt][0] = As[(r + g)     * 36 + 8 * ks + tig];
                a[mt][1] = As[(r + g + 8) * 36 + 8 * ks + tig];
                a[mt][2] = As[(r + g)     * 36 + 8 * ks + tig + 4];
                a[mt][3] = As[(r + g + 8) * 36 + 8 * ks + tig + 4];
            }
            #pragma unroll
            for (int t = 0; t < 8; t++) {
                b[t][0] = Bs[(8 * ks + tig)     * 136 + 64 * wn + 8 * t + g];
                b[t][1] = Bs[(8 * ks + tig + 4) * 136 + 64 * wn + 8 * t + g];
            }
            #pragma unroll
            for (int mt = 0; mt < 2; mt++)
                #pragma unroll
                for (int t = 0; t < 8; t++)
                    mma8(acc[mt][t], a[mt], b[t]);
        }
        __syncthreads();
    }

    #pragma unroll
    for (int mt = 0; mt < 2; mt++) {
        int r = m0 + 32 * wm + 16 * mt + g;
        #pragma unroll
        for (int t = 0; t < 8; t++) {
            int c = n0 + 64 * wn + 8 * t + 2 * tig;
            float2 r0 = make_float2(acc[mt][t][0] + bias[c], acc[mt][t][1] + bias[c + 1]);
            float2 r1 = make_float2(acc[mt][t][2] + bias[c], acc[mt][t][3] + bias[c + 1]);
            *(float2*)&out[(size_t)r * EMB + c]       = r0;
            *(float2*)&out[(size_t)(r + 8) * EMB + c] = r1;
        }
    }
}

extern "C" void kernel_launch(void* const* d_in, const int* in_sizes, int n_in,
                              void* d_out, int out_size)
{
    const float* x  = (const float*)d_in[0];
    const float* W1 = (const float*)d_in[1];
    const float* W2 = (const float*)d_in[2];
    const float* Wp = (const float*)d_in[3];
    const float* bp = (const float*)d_in[4];
    const float* nw = (const float*)d_in[5];
    const float* l1 = (const float*)d_in[6];
    const float* l2 = (const float*)d_in[7];
    // d_in[8] = xpos (int64) unused: attention is non-causal in the reference
    float* out = (float*)d_out;

    // QKV projections (v2 is dead in the reference -> only 1536 cols of W2)
    qkv_mma_kernel<<<dim3(18, 32), 256>>>(x, W1, 0);
    qkv_mma_kernel<<<dim3(12, 32), 256>>>(x, W2, 1);

    const size_t smem = (size_t)(2 * 128 * 68 + 2 * 64 * 68 + 64 * 72 + 2 * 128 * 68) * 4;
    cudaFuncSetAttribute(diff_attn_mma, cudaFuncAttributeMaxDynamicSharedMemorySize, (int)smem);
    diff_attn_mma<<<dim3(SEQ / 128, BSZ * NH), 256, smem>>>(l1, l2);

    rmsnorm_kernel<<<ROWS, 256>>>(nw);
    proj_mma_kernel<<<dim3(EMB / 128, ROWS / 128), 256>>>(Wp, bp, out);
}

// round 3
// speedup vs baseline: 4.8791x; 1.0342x over previous
#include <cuda_runtime.h>
#include <math.h>
#include <stdint.h>

#define BSZ 2
#define SEQ 2048
#define EMB 768
#define NH 12
#define HDIM 64
#define ROWS (BSZ*SEQ)

// Scratch (allocation-free rule: __device__ globals). Q/K/V stored pre-converted tf32 bits.
__device__ uint32_t g_q1u[BSZ*NH*SEQ*HDIM];
__device__ uint32_t g_k1u[BSZ*NH*SEQ*HDIM];
__device__ uint32_t g_v1u[BSZ*NH*SEQ*HDIM];
__device__ uint32_t g_q2u[BSZ*NH*SEQ*HDIM];
__device__ uint32_t g_k2u[BSZ*NH*SEQ*HDIM];
__device__ float g_att[ROWS*EMB];
__device__ float g_rms[ROWS];

// ---------------------------------------------------------------------------
// helpers
// ---------------------------------------------------------------------------
__device__ __forceinline__ uint32_t cvt_tf32(float x) {
    uint32_t u;
    asm("cvt.rna.tf32.f32 %0, %1;" : "=r"(u) : "f"(x));
    return u;
}
__device__ __forceinline__ float ex2f(float x) {
    float y;
    asm("ex2.approx.f32 %0, %1;" : "=f"(y) : "f"(x));
    return y;
}
__device__ __forceinline__ void mma8(float* c, const uint32_t* a, const uint32_t* b) {
    asm volatile(
        "mma.sync.aligned.m16n8k8.row.col.f32.tf32.tf32.f32 "
        "{%0,%1,%2,%3},{%4,%5,%6,%7},{%8,%9},{%0,%1,%2,%3};"
        : "+f"(c[0]), "+f"(c[1]), "+f"(c[2]), "+f"(c[3])
        : "r"(a[0]), "r"(a[1]), "r"(a[2]), "r"(a[3]), "r"(b[0]), "r"(b[1]));
}
#define CP16(dst_u32, src_ptr) \
    asm volatile("cp.async.cg.shared.global [%0], [%1], 16;" :: "r"(dst_u32), "l"(src_ptr))
#define CPCOMMIT() asm volatile("cp.async.commit_group;")

// 0.125 * log2(e): fold head-dim scale AND exp->exp2 conversion into Q
#define QSCALE 0.18033688011112042f

// ---------------------------------------------------------------------------
// Merged QKV projection GEMM (tf32 mma, register-prefetch double buffer).
// grid (30, 32): bx<18 -> W1 (2304 cols), bx>=18 -> W2 (first 1536 cols; v2 dead).
// Epilogue scatters tf32-converted values into [B,H,N,HD] tensors (Q pre-scaled).
// ---------------------------------------------------------------------------
__global__ __launch_bounds__(256) void qkv_mma_kernel(const float* __restrict__ X,
                                                      const float* __restrict__ W1,
                                                      const float* __restrict__ W2)
{
    __shared__ uint32_t As[128*36];
    __shared__ uint32_t Bs[32*136];

    const int tid  = threadIdx.x;
    const int lane = tid & 31, warp = tid >> 5;
    const int g = lane >> 2, tig = lane & 3;
    const int wm = warp >> 1, wn = warp & 1;
    const int m0 = blockIdx.y * 128;
    const bool second = blockIdx.x >= 18;
    const float* __restrict__ W = second ? W2 : W1;
    const int n0 = (second ? blockIdx.x - 18 : blockIdx.x) * 128;

    float acc[2][8][4] = {};
    float4 ra[4], rb[4];

    // prefetch kk=0
    #pragma unroll
    for (int it = 0; it < 4; it++) {
        int i = tid + it * 256;
        int rowA = i >> 3, cA = i & 7;
        ra[it] = *(const float4*)(X + (size_t)(m0 + rowA) * EMB + 4 * cA);
        int rowB = i >> 5, cB = i & 31;
        rb[it] = *(const float4*)(W + (size_t)rowB * 2304 + n0 + 4 * cB);
    }

    for (int kk = 0; kk < EMB; kk += 32) {
        #pragma unroll
        for (int it = 0; it < 4; it++) {
            int i = tid + it * 256;
            int rowA = i >> 3, cA = i & 7;
            uint32_t* d = &As[rowA * 36 + 4 * cA];
            d[0] = cvt_tf32(ra[it].x); d[1] = cvt_tf32(ra[it].y);
            d[2] = cvt_tf32(ra[it].z); d[3] = cvt_tf32(ra[it].w);
            int rowB = i >> 5, cB = i & 31;
            uint32_t* e = &Bs[rowB * 136 + 4 * cB];
            e[0] = cvt_tf32(rb[it].x); e[1] = cvt_tf32(rb[it].y);
            e[2] = cvt_tf32(rb[it].z); e[3] = cvt_tf32(rb[it].w);
        }
        __syncthreads();

        if (kk + 32 < EMB) {
            #pragma unroll
            for (int it = 0; it < 4; it++) {
                int i = tid + it * 256;
                int rowA = i >> 3, cA = i & 7;
                ra[it] = *(const float4*)(X + (size_t)(m0 + rowA) * EMB + kk + 32 + 4 * cA);
                int rowB = i >> 5, cB = i & 31;
                rb[it] = *(const float4*)(W + (size_t)(kk + 32 + rowB) * 2304 + n0 + 4 * cB);
            }
        }

        #pragma unroll
        for (int ks = 0; ks < 4; ks++) {
            uint32_t a[2][4], b[8][2];
            #pragma unroll
            for (int mt = 0; mt < 2; mt++) {
                int r = 32 * wm + 16 * mt;
                a[mt][0] = As[(r + g)     * 36 + 8 * ks + tig];
                a[mt][1] = As[(r + g + 8) * 36 + 8 * ks + tig];
                a[mt][2] = As[(r + g)     * 36 + 8 * ks + tig + 4];
                a[mt][3] = As[(r + g + 8) * 36 + 8 * ks + tig + 4];
            }
            #pragma unroll
            for (int t = 0; t < 8; t++) {
                b[t][0] = Bs[(8 * ks + tig)     * 136 + 64 * wn + 8 * t + g];
                b[t][1] = Bs[(8 * ks + tig + 4) * 136 + 64 * wn + 8 * t + g];
            }
            #pragma unroll
            for (int mt = 0; mt < 2; mt++)
                #pragma unroll
                for (int t = 0; t < 8; t++)
                    mma8(acc[mt][t], a[mt], b[t]);
        }
        __syncthreads();
    }

    // epilogue: scatter tf32 into Q/K/V ([B,H,N,HD])
    const int cbase = n0 + 64 * wn;   // multiple of 64 -> single (sel, head)
    const int sel = cbase / EMB;
    const int h = (cbase - sel * EMB) >> 6;
    uint32_t* dst = second ? (sel == 0 ? g_q2u : g_k2u)
                           : (sel == 0 ? g_q1u : (sel == 1 ? g_k1u : g_v1u));
    const float scl = (sel == 0) ? QSCALE : 1.0f;
    #pragma unroll
    for (int mt = 0; mt < 2; mt++) {
        int r = m0 + 32 * wm + 16 * mt + g;
        int bb = r >> 11, n = r & (SEQ - 1);
        size_t base = (size_t)(bb * NH + h) * SEQ;
        #pragma unroll
        for (int t = 0; t < 8; t++) {
            int d0 = 8 * t + 2 * tig;
            *(uint2*)&dst[(base + n) * HDIM + d0] =
                make_uint2(cvt_tf32(acc[mt][t][0] * scl), cvt_tf32(acc[mt][t][1] * scl));
            *(uint2*)&dst[(base + n + 8) * HDIM + d0] =
                make_uint2(cvt_tf32(acc[mt][t][2] * scl), cvt_tf32(acc[mt][t][3] * scl));
        }
    }
}

// ---------------------------------------------------------------------------
// Differential flash attention, tf32 mma, cp.async double-buffered K/V.
// q-tile 128 (8 warps x 16 rows), k-tile 64. Q1 fragments live in registers.
// ---------------------------------------------------------------------------
__device__ __forceinline__ void softmax_update(
    float s[8][4], float m[2], float l[2], float o[8][4],
    uint32_t* __restrict__ Ps, int warp, int g, int tig)
{
    #pragma unroll
    for (int rr = 0; rr < 2; rr++) {
        const int i0 = rr * 2, i1 = rr * 2 + 1;
        float tm = -1e30f;
        #pragma unroll
        for (int t = 0; t < 8; t++) tm = fmaxf(tm, fmaxf(s[t][i0], s[t][i1]));
        tm = fmaxf(tm, __shfl_xor_sync(0xffffffffu, tm, 1));
        tm = fmaxf(tm, __shfl_xor_sync(0xffffffffu, tm, 2));
        float nm = fmaxf(m[rr], tm);
        float corr = ex2f(m[rr] - nm);
        float rs = 0.f;
        #pragma unroll
        for (int t = 0; t < 8; t++) {
            float p0 = ex2f(s[t][i0] - nm);
            float p1 = ex2f(s[t][i1] - nm);
            s[t][i0] = p0; s[t][i1] = p1;
            rs += p0 + p1;
        }
        rs += __shfl_xor_sync(0xffffffffu, rs, 1);
        rs += __shfl_xor_sync(0xffffffffu, rs, 2);
        l[rr] = l[rr] * corr + rs;
        m[rr] = nm;
        #pragma unroll
        for (int t = 0; t < 8; t++) { o[t][i0] *= corr; o[t][i1] *= corr; }
        const int row = 16 * warp + g + 8 * rr;
        #pragma unroll
        for (int t = 0; t < 8; t++) {
            uint2 pk = make_uint2(cvt_tf32(s[t][i0]), cvt_tf32(s[t][i1]));
            *(uint2*)&Ps[row * 68 + 8 * t + 2 * tig] = pk;
        }
    }
}

__global__ __launch_bounds__(256) void diff_attn_mma(const float* __restrict__ lam1,
                                                     const float* __restrict__ lam2)
{
    extern __shared__ uint32_t sm[];
    uint32_t* Q2s = sm;                  // 128x68
    uint32_t* K1s = Q2s + 128 * 68;      // 2 x 64x68
    uint32_t* K2s = K1s + 2 * 4352;      // 2 x 64x68
    uint32_t* Vs  = K2s + 2 * 4352;      // 2 x 64x72
    uint32_t* P1s = Vs  + 2 * 4608;      // 128x68
    uint32_t* P2s = P1s + 128 * 68;      // 128x68

    const int tid  = threadIdx.x;
    const int lane = tid & 31, warp = tid >> 5;
    const int g = lane >> 2, tig = lane & 3;
    const int bh = blockIdx.y;
    const int b = bh / NH, h = bh - b * NH;
    const int q0 = blockIdx.x * 128;
    const int r = 16 * warp;

    const uint32_t* Q1g = g_q1u + ((size_t)bh * SEQ + q0) * HDIM;
    const uint32_t* Q2g = g_q2u + ((size_t)bh * SEQ + q0) * HDIM;
    const uint32_t* K1g = g_k1u + (size_t)bh * SEQ * HDIM;
    const uint32_t* K2g = g_k2u + (size_t)bh * SEQ * HDIM;
    const uint32_t* V1g = g_v1u + (size_t)bh * SEQ * HDIM;

    // Q2 tile -> smem (raw tf32 copy)
    #pragma unroll
    for (int it = 0; it < 8; it++) {
        int i = tid + it * 256;
        int row = i >> 4, c4 = i & 15;
        *(uint4*)&Q2s[row * 68 + 4 * c4] = *(const uint4*)(Q2g + row * 64 + 4 * c4);
    }
    // Q1 fragments -> registers (warp-private rows)
    uint32_t q1f[8][4];
    #pragma unroll
    for (int ks = 0; ks < 8; ks++) {
        q1f[ks][0] = Q1g[(r + g)     * 64 + 8 * ks + tig];
        q1f[ks][1] = Q1g[(r + g + 8) * 64 + 8 * ks + tig];
        q1f[ks][2] = Q1g[(r + g)     * 64 + 8 * ks + tig + 4];
        q1f[ks][3] = Q1g[(r + g + 8) * 64 + 8 * ks + tig + 4];
    }

    const uint32_t smb = (uint32_t)__cvta_generic_to_shared(sm);
    const uint32_t K1b = smb + 8704u * 4;
    const uint32_t K2b = K1b + 2u * 4352 * 4;
    const uint32_t Vb  = K2b + 2u * 4352 * 4;

    auto prefetch = [&](int kt, int buf) {
        const uint32_t* k1p = K1g + (size_t)kt * 64 * 64;
        const uint32_t* k2p = K2g + (size_t)kt * 64 * 64;
        const uint32_t* vp  = V1g + (size_t)kt * 64 * 64;
        #pragma unroll
        for (int it = 0; it < 4; it++) {
            int c = tid + it * 256;
            int row = c >> 4, q4 = (c & 15) * 4;
            CP16(K1b + (uint32_t)(buf * 4352 + row * 68 + q4) * 4, k1p + row * 64 + q4);
            CP16(K2b + (uint32_t)(buf * 4352 + row * 68 + q4) * 4, k2p + row * 64 + q4);
            CP16(Vb  + (uint32_t)(buf * 4608 + row * 72 + q4) * 4, vp  + row * 64 + q4);
        }
        CPCOMMIT();
    };

    prefetch(0, 0);

    float o1[8][4] = {}, o2[8][4] = {};
    float m1[2] = {-1e30f, -1e30f}, m2[2] = {-1e30f, -1e30f};
    float l1v[2] = {0.f, 0.f}, l2v[2] = {0.f, 0.f};

    for (int kt = 0; kt < SEQ / 64; kt++) {
        const int cur = kt & 1;
        if (kt + 1 < SEQ / 64) {
            prefetch(kt + 1, cur ^ 1);
            asm volatile("cp.async.wait_group 1;");
        } else {
            asm volatile("cp.async.wait_group 0;");
        }
        __syncthreads();

        const uint32_t* K1c = K1s + cur * 4352;
        const uint32_t* K2c = K2s + cur * 4352;
        const uint32_t* Vc  = Vs  + cur * 4608;

        // ---- attn1: S1 = Q1 K1^T (Q1 from registers) ----
        {
            float s1[8][4] = {};
            #pragma unroll
            for (int ks = 0; ks < 8; ks++) {
                #pragma unroll
                for (int t = 0; t < 8; t++) {
                    uint32_t bk[2];
                    bk[0] = K1c[(8 * t + g) * 68 + 8 * ks + tig];
                    bk[1] = K1c[(8 * t + g) * 68 + 8 * ks + tig + 4];
                    mma8(s1[t], q1f[ks], bk);
                }
            }
            softmax_update(s1, m1, l1v, o1, P1s, warp, g, tig);
        }
        // ---- attn2: S2 = Q2 K2^T ----
        {
            float s2[8][4] = {};
            #pragma unroll
            for (int ks = 0; ks < 8; ks++) {
                uint32_t aq[4];
                aq[0] = Q2s[(r + g)     * 68 + 8 * ks + tig];
                aq[1] = Q2s[(r + g + 8) * 68 + 8 * ks + tig];
                aq[2] = Q2s[(r + g)     * 68 + 8 * ks + tig + 4];
                aq[3] = Q2s[(r + g + 8) * 68 + 8 * ks + tig + 4];
                #pragma unroll
                for (int t = 0; t < 8; t++) {
                    uint32_t bk[2];
                    bk[0] = K2c[(8 * t + g) * 68 + 8 * ks + tig];
                    bk[1] = K2c[(8 * t + g) * 68 + 8 * ks + tig + 4];
                    mma8(s2[t], aq, bk);
                }
            }
            softmax_update(s2, m2, l2v, o2, P2s, warp, g, tig);
        }
        __syncwarp();

        // ---- O += P @ V (V shared; P rows are warp-private) ----
        #pragma unroll
        for (int ks = 0; ks < 8; ks++) {
            uint32_t a1[4], a2[4];
            a1[0] = P1s[(r + g)     * 68 + 8 * ks + tig];
            a1[1] = P1s[(r + g + 8) * 68 + 8 * ks + tig];
            a1[2] = P1s[(r + g)     * 68 + 8 * ks + tig + 4];
            a1[3] = P1s[(r + g + 8) * 68 + 8 * ks + tig + 4];
            a2[0] = P2s[(r + g)     * 68 + 8 * ks + tig];
            a2[1] = P2s[(r + g + 8) * 68 + 8 * ks + tig];
            a2[2] = P2s[(r + g)     * 68 + 8 * ks + tig + 4];
            a2[3] = P2s[(r + g + 8) * 68 + 8 * ks + tig + 4];
            #pragma unroll
            for (int t = 0; t < 8; t++) {
                uint32_t bv[2];
                bv[0] = Vc[(8 * ks + tig)     * 72 + 8 * t + g];
                bv[1] = Vc[(8 * ks + tig + 4) * 72 + 8 * t + g];
                mma8(o1[t], a1, bv);
                mma8(o2[t], a2, bv);
            }
        }
        __syncthreads();
    }

    // epilogue
    const float lam = lam1[h] - lam2[h] + 0.1f;
    const float i10 = 1.f / l1v[0], i11 = 1.f / l1v[1];
    const float i20 = 1.f / l2v[0], i21 = 1.f / l2v[1];
    const int n = q0 + 16 * warp + g;
    #pragma unroll
    for (int t = 0; t < 8; t++) {
        const int col = h * HDIM + 8 * t + 2 * tig;
        float2 r0 = make_float2(o1[t][0] * i10 - lam * o2[t][0] * i20,
                                o1[t][1] * i10 - lam * o2[t][1] * i20);
        float2 r1 = make_float2(o1[t][2] * i11 - lam * o2[t][2] * i21,
                                o1[t][3] * i11 - lam * o2[t][3] * i21);
        *(float2*)&g_att[((size_t)(b * SEQ + n)) * EMB + col]     = r0;
        *(float2*)&g_att[((size_t)(b * SEQ + n + 8)) * EMB + col] = r1;
    }
}

// ---------------------------------------------------------------------------
// Per-row inverse RMS (warp per row)
// ---------------------------------------------------------------------------
__global__ void rms_kernel()
{
    const int lane = threadIdx.x & 31, warp = threadIdx.x >> 5;
    const int row = blockIdx.x * 8 + warp;
    const float* p = g_att + (size_t)row * EMB;
    float ss = 0.f;
    #pragma unroll
    for (int i = 0; i < 6; i++) {
        float4 v = *(const float4*)(p + lane * 4 + i * 128);
        ss += v.x * v.x + v.y * v.y + v.z * v.z + v.w * v.w;
    }
    #pragma unroll
    for (int off = 16; off > 0; off >>= 1)
        ss += __shfl_xor_sync(0xffffffffu, ss, off);
    if (lane == 0) g_rms[row] = rsqrtf(ss * (1.0f / EMB) + 1e-6f);
}

// ---------------------------------------------------------------------------
// Output projection with fused RMSNorm: out = (att*rms*nw) @ Wp + bias
// ---------------------------------------------------------------------------
__global__ __launch_bounds__(256) void proj_mma_kernel(const float* __restrict__ W,
                                                       const float* __restrict__ bias,
                                                       const float* __restrict__ nw,
                                                       float* __restrict__ out)
{
    __shared__ uint32_t As[128*36];
    __shared__ uint32_t Bs[32*136];

    const int tid  = threadIdx.x;
    const int lane = tid & 31, warp = tid >> 5;
    const int g = lane >> 2, tig = lane & 3;
    const int wm = warp >> 1, wn = warp & 1;
    const int m0 = blockIdx.y * 128, n0 = blockIdx.x * 128;

    float acc[2][8][4] = {};
    float rmsr[4];
    #pragma unroll
    for (int it = 0; it < 4; it++) {
        int i = tid + it * 256;
        rmsr[it] = g_rms[m0 + (i >> 3)];
    }

    float4 ra[4], rn[4], rb[4];
    #pragma unroll
    for (int it = 0; it < 4; it++) {
        int i = tid + it * 256;
        int rowA = i >> 3, cA = i & 7;
        ra[it] = *(const float4*)(g_att + (size_t)(m0 + rowA) * EMB + 4 * cA);
        rn[it] = *(const float4*)(nw + 4 * cA);
        int rowB = i >> 5, cB = i & 31;
        rb[it] = *(const float4*)(W + (size_t)rowB * EMB + n0 + 4 * cB);
    }

    for (int kk = 0; kk < EMB; kk += 32) {
        #pragma unroll
        for (int it = 0; it < 4; it++) {
            int i = tid + it * 256;
            int rowA = i >> 3, cA = i & 7;
            uint32_t* d = &As[rowA * 36 + 4 * cA];
            d[0] = cvt_tf32(ra[it].x * rmsr[it] * rn[it].x);
            d[1] = cvt_tf32(ra[it].y * rmsr[it] * rn[it].y);
            d[2] = cvt_tf32(ra[it].z * rmsr[it] * rn[it].z);
            d[3] = cvt_tf32(ra[it].w * rmsr[it] * rn[it].w);
            int rowB = i >> 5, cB = i & 31;
            uint32_t* e = &Bs[rowB * 136 + 4 * cB];
            e[0] = cvt_tf32(rb[it].x); e[1] = cvt_tf32(rb[it].y);
            e[2] = cvt_tf32(rb[it].z); e[3] = cvt_tf32(rb[it].w);
        }
        __syncthreads();

        if (kk + 32 < EMB) {
            #pragma unroll
            for (int it = 0; it < 4; it++) {
                int i = tid + it * 256;
                int rowA = i >> 3, cA = i & 7;
                ra[it] = *(const float4*)(g_att + (size_t)(m0 + rowA) * EMB + kk + 32 + 4 * cA);
                rn[it] = *(const float4*)(nw + kk + 32 + 4 * cA);
                int rowB = i >> 5, cB = i & 31;
                rb[it] = *(const float4*)(W + (size_t)(kk + 32 + rowB) * EMB + n0 + 4 * cB);
            }
        }

        #pragma unroll
        for (int ks = 0; ks < 4; ks++) {
            uint32_t a[2][4], b[8][2];
            #pragma unroll
            for (int mt = 0; mt < 2; mt++) {
                int r = 32 * wm + 16 * mt;
                a[mt][0] = As[(r + g)     * 36 + 8 * ks + tig];
                a[mt][1] = As[(r + g + 8) * 36 + 8 * ks + tig];
                a[mt][2] = As[(r + g)     * 36 + 8 * ks + tig + 4];
                a[mt][3] = As[(r + g + 8) * 36 + 8 * ks + tig + 4];
            }
            #pragma unroll
            for (int t = 0; t < 8; t++) {
                b[t][0] = Bs[(8 * ks + tig)     * 136 + 64 * wn + 8 * t + g];
                b[t][1] = Bs[(8 * ks + tig + 4) * 136 + 64 * wn + 8 * t + g];
            }
            #pragma unroll
            for (int mt = 0; mt < 2; mt++)
                #pragma unroll
                for (int t = 0; t < 8; t++)
                    mma8(acc[mt][t], a[mt], b[t]);
        }
        __syncthreads();
    }

    #pragma unroll
    for (int mt = 0; mt < 2; mt++) {
        int r = m0 + 32 * wm + 16 * mt + g;
        #pragma unroll
        for (int t = 0; t < 8; t++) {
            int c = n0 + 64 * wn + 8 * t + 2 * tig;
            float2 r0 = make_float2(acc[mt][t][0] + bias[c], acc[mt][t][1] + bias[c + 1]);
            float2 r1 = make_float2(acc[mt][t][2] + bias[c], acc[mt][t][3] + bias[c + 1]);
            *(float2*)&out[(size_t)r * EMB + c]       = r0;
            *(float2*)&out[(size_t)(r + 8) * EMB + c] = r1;
        }
    }
}

extern "C" void kernel_launch(void* const* d_in, const int* in_sizes, int n_in,
                              void* d_out, int out_size)
{
    const float* x  = (const float*)d_in[0];
    const float* W1 = (const float*)d_in[1];
    const float* W2 = (const float*)d_in[2];
    const float* Wp = (const float*)d_in[3];
    const float* bp = (const float*)d_in[4];
    const float* nw = (const float*)d_in[5];
    const float* l1 = (const float*)d_in[6];
    const float* l2 = (const float*)d_in[7];
    // d_in[8] = xpos (int64) unused: attention is non-causal in the reference
    float* out = (float*)d_out;

    qkv_mma_kernel<<<dim3(30, 32), 256>>>(x, W1, W2);

    const size_t smem = (size_t)(128*68 + 2*4352 + 2*4352 + 2*4608 + 2*128*68) * 4; // 210944 B
    cudaFuncSetAttribute(diff_attn_mma, cudaFuncAttributeMaxDynamicSharedMemorySize, (int)smem);
    diff_attn_mma<<<dim3(SEQ / 128, BSZ * NH), 256, smem>>>(l1, l2);

    rms_kernel<<<ROWS / 8, 256>>>();
    proj_mma_kernel<<<dim3(EMB / 128, ROWS / 128), 256>>>(Wp, bp, nw, out);
}

// round 5
// speedup vs baseline: 5.0891x; 1.0430x over previous
#include <cuda_runtime.h>
#include <math.h>
#include <stdint.h>

#define BSZ 2
#define SEQ 2048
#define EMB 768
#define NH 12
#define HDIM 64
#define ROWS (BSZ*SEQ)

// Scratch (allocation-free rule: __device__ globals). Q/K/V stored pre-converted tf32 bits.
__device__ uint32_t g_q1u[BSZ*NH*SEQ*HDIM];
__device__ uint32_t g_k1u[BSZ*NH*SEQ*HDIM];
__device__ uint32_t g_v1u[BSZ*NH*SEQ*HDIM];
__device__ uint32_t g_q2u[BSZ*NH*SEQ*HDIM];
__device__ uint32_t g_k2u[BSZ*NH*SEQ*HDIM];
__device__ float g_att[ROWS*EMB];
__device__ float g_rms[ROWS];

// ---------------------------------------------------------------------------
// helpers
// ---------------------------------------------------------------------------
__device__ __forceinline__ uint32_t cvt_tf32(float x) {
    uint32_t u;
    asm("cvt.rna.tf32.f32 %0, %1;" : "=r"(u) : "f"(x));
    return u;
}
__device__ __forceinline__ float ex2f(float x) {
    float y;
    asm("ex2.approx.f32 %0, %1;" : "=f"(y) : "f"(x));
    return y;
}
__device__ __forceinline__ void mma8(float* c, const uint32_t* a, const uint32_t* b) {
    asm volatile(
        "mma.sync.aligned.m16n8k8.row.col.f32.tf32.tf32.f32 "
        "{%0,%1,%2,%3},{%4,%5,%6,%7},{%8,%9},{%0,%1,%2,%3};"
        : "+f"(c[0]), "+f"(c[1]), "+f"(c[2]), "+f"(c[3])
        : "r"(a[0]), "r"(a[1]), "r"(a[2]), "r"(a[3]), "r"(b[0]), "r"(b[1]));
}
#define CP16(dst_u32, src_ptr) \
    asm volatile("cp.async.cg.shared.global [%0], [%1], 16;" :: "r"(dst_u32), "l"(src_ptr))
#define CPCOMMIT() asm volatile("cp.async.commit_group;")

// 0.125 * log2(e): fold head-dim scale AND exp->exp2 conversion into Q
#define QSCALE 0.18033688011112042f

// ---------------------------------------------------------------------------
// Merged QKV projection GEMM (tf32 mma, register-prefetch double buffer).
// ---------------------------------------------------------------------------
__global__ __launch_bounds__(256) void qkv_mma_kernel(const float* __restrict__ X,
                                                      const float* __restrict__ W1,
                                                      const float* __restrict__ W2)
{
    __shared__ uint32_t As[128*36];
    __shared__ uint32_t Bs[32*136];

    const int tid  = threadIdx.x;
    const int lane = tid & 31, warp = tid >> 5;
    const int g = lane >> 2, tig = lane & 3;
    const int wm = warp >> 1, wn = warp & 1;
    const int m0 = blockIdx.y * 128;
    const bool second = blockIdx.x >= 18;
    const float* __restrict__ W = second ? W2 : W1;
    const int n0 = (second ? blockIdx.x - 18 : blockIdx.x) * 128;

    float acc[2][8][4] = {};
    float4 ra[4], rb[4];

    #pragma unroll
    for (int it = 0; it < 4; it++) {
        int i = tid + it * 256;
        int rowA = i >> 3, cA = i & 7;
        ra[it] = *(const float4*)(X + (size_t)(m0 + rowA) * EMB + 4 * cA);
        int rowB = i >> 5, cB = i & 31;
        rb[it] = *(const float4*)(W + (size_t)rowB * 2304 + n0 + 4 * cB);
    }

    for (int kk = 0; kk < EMB; kk += 32) {
        #pragma unroll
        for (int it = 0; it < 4; it++) {
            int i = tid + it * 256;
            int rowA = i >> 3, cA = i & 7;
            uint32_t* d = &As[rowA * 36 + 4 * cA];
            d[0] = cvt_tf32(ra[it].x); d[1] = cvt_tf32(ra[it].y);
            d[2] = cvt_tf32(ra[it].z); d[3] = cvt_tf32(ra[it].w);
            int rowB = i >> 5, cB = i & 31;
            uint32_t* e = &Bs[rowB * 136 + 4 * cB];
            e[0] = cvt_tf32(rb[it].x); e[1] = cvt_tf32(rb[it].y);
            e[2] = cvt_tf32(rb[it].z); e[3] = cvt_tf32(rb[it].w);
        }
        __syncthreads();

        if (kk + 32 < EMB) {
            #pragma unroll
            for (int it = 0; it < 4; it++) {
                int i = tid + it * 256;
                int rowA = i >> 3, cA = i & 7;
                ra[it] = *(const float4*)(X + (size_t)(m0 + rowA) * EMB + kk + 32 + 4 * cA);
                int rowB = i >> 5, cB = i & 31;
                rb[it] = *(const float4*)(W + (size_t)(kk + 32 + rowB) * 2304 + n0 + 4 * cB);
            }
        }

        #pragma unroll
        for (int ks = 0; ks < 4; ks++) {
            uint32_t a[2][4], b[8][2];
            #pragma unroll
            for (int mt = 0; mt < 2; mt++) {
                int r = 32 * wm + 16 * mt;
                a[mt][0] = As[(r + g)     * 36 + 8 * ks + tig];
                a[mt][1] = As[(r + g + 8) * 36 + 8 * ks + tig];
                a[mt][2] = As[(r + g)     * 36 + 8 * ks + tig + 4];
                a[mt][3] = As[(r + g + 8) * 36 + 8 * ks + tig + 4];
            }
            #pragma unroll
            for (int t = 0; t < 8; t++) {
                b[t][0] = Bs[(8 * ks + tig)     * 136 + 64 * wn + 8 * t + g];
                b[t][1] = Bs[(8 * ks + tig + 4) * 136 + 64 * wn + 8 * t + g];
            }
            #pragma unroll
            for (int mt = 0; mt < 2; mt++)
                #pragma unroll
                for (int t = 0; t < 8; t++)
                    mma8(acc[mt][t], a[mt], b[t]);
        }
        __syncthreads();
    }

    const int cbase = n0 + 64 * wn;
    const int sel = cbase / EMB;
    const int h = (cbase - sel * EMB) >> 6;
    uint32_t* dst = second ? (sel == 0 ? g_q2u : g_k2u)
                           : (sel == 0 ? g_q1u : (sel == 1 ? g_k1u : g_v1u));
    const float scl = (sel == 0) ? QSCALE : 1.0f;
    #pragma unroll
    for (int mt = 0; mt < 2; mt++) {
        int r = m0 + 32 * wm + 16 * mt + g;
        int bb = r >> 11, n = r & (SEQ - 1);
        size_t base = (size_t)(bb * NH + h) * SEQ;
        #pragma unroll
        for (int t = 0; t < 8; t++) {
            int d0 = 8 * t + 2 * tig;
            *(uint2*)&dst[(base + n) * HDIM + d0] =
                make_uint2(cvt_tf32(acc[mt][t][0] * scl), cvt_tf32(acc[mt][t][1] * scl));
            *(uint2*)&dst[(base + n + 8) * HDIM + d0] =
                make_uint2(cvt_tf32(acc[mt][t][2] * scl), cvt_tf32(acc[mt][t][3] * scl));
        }
    }
}

// ---------------------------------------------------------------------------
// Differential flash attention, tf32 mma, 512 threads (16 warps), k-split.
// warp (qg = warp&7, kh = warp>>3): 16 q-rows x 32 k-cols. No online max
// (scores bounded); l and O partials reduced once at the end.
// P regions are indexed by kh (the R4 race fix). K1/K2 double-buffered via
// cp.async; V single-buffered (its latency is hidden behind S+softmax).
// ---------------------------------------------------------------------------
__global__ __launch_bounds__(512) void diff_attn_mma(const float* __restrict__ lam1,
                                                     const float* __restrict__ lam2)
{
    extern __shared__ uint32_t sm[];
    uint32_t* Q1s = sm;                 // 128x68 = 8704
    uint32_t* Q2s = sm + 8704;          // 8704
    uint32_t* K1s = sm + 17408;         // 2 x 64x68 = 8704
    uint32_t* K2s = sm + 26112;         // 8704
    uint32_t* Vs  = sm + 34816;         // 64x72 = 4608 (single buffer)
    uint32_t* P1s = sm + 39424;         // 2(kh) x 128x36 = 9216
    uint32_t* P2s = sm + 48640;         // 9216   total 57856 w = 231424 B

    const int tid  = threadIdx.x;
    const int lane = tid & 31, warp = tid >> 5;
    const int g = lane >> 2, tig = lane & 3;
    const int qg = warp & 7, kh = warp >> 3;
    const int r = 16 * qg;
    const int pbase = kh * 4608;        // kh-private P region
    const int bh = blockIdx.y;
    const int b = bh / NH, h = bh - b * NH;
    const int q0 = blockIdx.x * 128;

    const uint32_t* Q1g = g_q1u + ((size_t)bh * SEQ + q0) * HDIM;
    const uint32_t* Q2g = g_q2u + ((size_t)bh * SEQ + q0) * HDIM;
    const uint32_t* K1g = g_k1u + (size_t)bh * SEQ * HDIM;
    const uint32_t* K2g = g_k2u + (size_t)bh * SEQ * HDIM;
    const uint32_t* V1g = g_v1u + (size_t)bh * SEQ * HDIM;

    // Q tiles -> smem (raw tf32 copy; scale pre-folded)
    #pragma unroll
    for (int it = 0; it < 4; it++) {
        int i = tid + it * 512;
        int row = i >> 4, c4 = i & 15;
        *(uint4*)&Q1s[row * 68 + 4 * c4] = *(const uint4*)(Q1g + row * 64 + 4 * c4);
        *(uint4*)&Q2s[row * 68 + 4 * c4] = *(const uint4*)(Q2g + row * 64 + 4 * c4);
    }

    const uint32_t smb = (uint32_t)__cvta_generic_to_shared(sm);
    const uint32_t K1b = smb + 17408u * 4;
    const uint32_t K2b = smb + 26112u * 4;
    const uint32_t Vb  = smb + 34816u * 4;

    auto prefetch_K = [&](int kt, int buf) {
        const uint32_t* k1p = K1g + (size_t)kt * 4096;
        const uint32_t* k2p = K2g + (size_t)kt * 4096;
        #pragma unroll
        for (int it = 0; it < 2; it++) {
            int c = tid + it * 512;
            int row = c >> 4, q4 = (c & 15) * 4;
            CP16(K1b + (uint32_t)(buf * 4352 + row * 68 + q4) * 4, k1p + row * 64 + q4);
            CP16(K2b + (uint32_t)(buf * 4352 + row * 68 + q4) * 4, k2p + row * 64 + q4);
        }
        CPCOMMIT();
    };
    auto prefetch_V = [&](int kt) {
        const uint32_t* vp = V1g + (size_t)kt * 4096;
        #pragma unroll
        for (int it = 0; it < 2; it++) {
            int c = tid + it * 512;
            int row = c >> 4, q4 = (c & 15) * 4;
            CP16(Vb + (uint32_t)(row * 72 + q4) * 4, vp + row * 64 + q4);
        }
        CPCOMMIT();
    };

    prefetch_K(0, 0);

    float o1[8][4] = {}, o2[8][4] = {};
    float l1[2] = {0.f, 0.f}, l2[2] = {0.f, 0.f};

    const int NT = SEQ / 64;
    for (int kt = 0; kt < NT; kt++) {
        const int cur = kt & 1;
        const bool more = (kt + 1 < NT);
        // previous iter ends with __syncthreads -> safe to overwrite V buffer
        prefetch_V(kt);
        if (more) {
            prefetch_K(kt + 1, cur ^ 1);
            asm volatile("cp.async.wait_group 2;");   // K(cur) done; V(kt), K(kt+1) pending
        } else {
            asm volatile("cp.async.wait_group 1;");   // K(cur) done; V(kt) pending
        }
        __syncthreads();

        const uint32_t* K1c = K1s + cur * 4352;
        const uint32_t* K2c = K2s + cur * 4352;

        // ---- attn1: S1 = Q1 K1^T on this warp's 32 k-cols ----
        {
            float s1[4][4] = {};
            #pragma unroll
            for (int ks = 0; ks < 8; ks++) {
                uint32_t aq[4];
                aq[0] = Q1s[(r + g)     * 68 + 8 * ks + tig];
                aq[1] = Q1s[(r + g + 8) * 68 + 8 * ks + tig];
                aq[2] = Q1s[(r + g)     * 68 + 8 * ks + tig + 4];
                aq[3] = Q1s[(r + g + 8) * 68 + 8 * ks + tig + 4];
                #pragma unroll
                for (int t = 0; t < 4; t++) {
                    uint32_t bk[2];
                    int kr = 8 * (4 * kh + t) + g;
                    bk[0] = K1c[kr * 68 + 8 * ks + tig];
                    bk[1] = K1c[kr * 68 + 8 * ks + tig + 4];
                    mma8(s1[t], aq, bk);
                }
            }
            #pragma unroll
            for (int rr = 0; rr < 2; rr++) {
                float rs = 0.f;
                const int row = r + g + 8 * rr;
                #pragma unroll
                for (int t = 0; t < 4; t++) {
                    float p0 = ex2f(s1[t][2 * rr]);
                    float p1 = ex2f(s1[t][2 * rr + 1]);
                    rs += p0 + p1;
                    *(uint2*)&P1s[pbase + row * 36 + 8 * t + 2 * tig] =
                        make_uint2(cvt_tf32(p0), cvt_tf32(p1));
                }
                l1[rr] += rs;
            }
        }
        // ---- attn2 ----
        {
            float s2[4][4] = {};
            #pragma unroll
            for (int ks = 0; ks < 8; ks++) {
                uint32_t aq[4];
                aq[0] = Q2s[(r + g)     * 68 + 8 * ks + tig];
                aq[1] = Q2s[(r + g + 8) * 68 + 8 * ks + tig];
                aq[2] = Q2s[(r + g)     * 68 + 8 * ks + tig + 4];
                aq[3] = Q2s[(r + g + 8) * 68 + 8 * ks + tig + 4];
                #pragma unroll
                for (int t = 0; t < 4; t++) {
                    uint32_t bk[2];
                    int kr = 8 * (4 * kh + t) + g;
                    bk[0] = K2c[kr * 68 + 8 * ks + tig];
                    bk[1] = K2c[kr * 68 + 8 * ks + tig + 4];
                    mma8(s2[t], aq, bk);
                }
            }
            #pragma unroll
            for (int rr = 0; rr < 2; rr++) {
                float rs = 0.f;
                const int row = r + g + 8 * rr;
                #pragma unroll
                for (int t = 0; t < 4; t++) {
                    float p0 = ex2f(s2[t][2 * rr]);
                    float p1 = ex2f(s2[t][2 * rr + 1]);
                    rs += p0 + p1;
                    *(uint2*)&P2s[pbase + row * 36 + 8 * t + 2 * tig] =
                        make_uint2(cvt_tf32(p0), cvt_tf32(p1));
                }
                l2[rr] += rs;
            }
        }
        __syncwarp();   // P regions are (qg, kh)-private; intra-warp visibility only

        // V must be resident before P@V (cp.asyncs from all threads + barrier)
        if (more) {
            asm volatile("cp.async.wait_group 1;");
        } else {
            asm volatile("cp.async.wait_group 0;");
        }
        __syncthreads();

        // ---- partial O += P(own 32 k-cols) @ V ----
        #pragma unroll
        for (int ks = 0; ks < 4; ks++) {
            uint32_t a1[4], a2[4];
            a1[0] = P1s[pbase + (r + g)     * 36 + 8 * ks + tig];
            a1[1] = P1s[pbase + (r + g + 8) * 36 + 8 * ks + tig];
            a1[2] = P1s[pbase + (r + g)     * 36 + 8 * ks + tig + 4];
            a1[3] = P1s[pbase + (r + g + 8) * 36 + 8 * ks + tig + 4];
            a2[0] = P2s[pbase + (r + g)     * 36 + 8 * ks + tig];
            a2[1] = P2s[pbase + (r + g + 8) * 36 + 8 * ks + tig];
            a2[2] = P2s[pbase + (r + g)     * 36 + 8 * ks + tig + 4];
            a2[3] = P2s[pbase + (r + g + 8) * 36 + 8 * ks + tig + 4];
            #pragma unroll
            for (int t = 0; t < 8; t++) {
                uint32_t bv[2];
                bv[0] = Vs[(32 * kh + 8 * ks + tig)     * 72 + 8 * t + g];
                bv[1] = Vs[(32 * kh + 8 * ks + tig + 4) * 72 + 8 * t + g];
                mma8(o1[t], a1, bv);
                mma8(o2[t], a2, bv);
            }
        }
        __syncthreads();
    }

    // ---- final reduction across tig lanes (l) and kh warp pairs (l, O) ----
    #pragma unroll
    for (int rr = 0; rr < 2; rr++) {
        l1[rr] += __shfl_xor_sync(0xffffffffu, l1[rr], 1);
        l1[rr] += __shfl_xor_sync(0xffffffffu, l1[rr], 2);
        l2[rr] += __shfl_xor_sync(0xffffffffu, l2[rr], 1);
        l2[rr] += __shfl_xor_sync(0xffffffffu, l2[rr], 2);
    }
    float* ob1 = (float*)K1s;   // 128x68 scratch
    float* ob2 = (float*)K2s;
    float* lbuf = (float*)Vs;   // [attn*128 + row]
    if (kh == 1) {
        #pragma unroll
        for (int t = 0; t < 8; t++) {
            *(float2*)&ob1[(r + g)     * 68 + 8 * t + 2 * tig] = make_float2(o1[t][0], o1[t][1]);
            *(float2*)&ob1[(r + g + 8) * 68 + 8 * t + 2 * tig] = make_float2(o1[t][2], o1[t][3]);
            *(float2*)&ob2[(r + g)     * 68 + 8 * t + 2 * tig] = make_float2(o2[t][0], o2[t][1]);
            *(float2*)&ob2[(r + g + 8) * 68 + 8 * t + 2 * tig] = make_float2(o2[t][2], o2[t][3]);
        }
        if (tig == 0) {
            lbuf[r + g]           = l1[0];
            lbuf[r + g + 8]       = l1[1];
            lbuf[128 + r + g]     = l2[0];
            lbuf[128 + r + g + 8] = l2[1];
        }
    }
    __syncthreads();
    if (kh == 0) {
        const float lam = lam1[h] - lam2[h] + 0.1f;
        const float i10 = 1.f / (l1[0] + lbuf[r + g]);
        const float i11 = 1.f / (l1[1] + lbuf[r + g + 8]);
        const float i20 = 1.f / (l2[0] + lbuf[128 + r + g]);
        const float i21 = 1.f / (l2[1] + lbuf[128 + r + g + 8]);
        const int n = q0 + r + g;
        #pragma unroll
        for (int t = 0; t < 8; t++) {
            const int col = h * HDIM + 8 * t + 2 * tig;
            float2 p10 = *(float2*)&ob1[(r + g)     * 68 + 8 * t + 2 * tig];
            float2 p11 = *(float2*)&ob1[(r + g + 8) * 68 + 8 * t + 2 * tig];
            float2 p20 = *(float2*)&ob2[(r + g)     * 68 + 8 * t + 2 * tig];
            float2 p21 = *(float2*)&ob2[(r + g + 8) * 68 + 8 * t + 2 * tig];
            float2 r0 = make_float2((o1[t][0] + p10.x) * i10 - lam * (o2[t][0] + p20.x) * i20,
                                    (o1[t][1] + p10.y) * i10 - lam * (o2[t][1] + p20.y) * i20);
            float2 r1 = make_float2((o1[t][2] + p11.x) * i11 - lam * (o2[t][2] + p21.x) * i21,
                                    (o1[t][3] + p11.y) * i11 - lam * (o2[t][3] + p21.y) * i21);
            *(float2*)&g_att[((size_t)(b * SEQ + n)) * EMB + col]     = r0;
            *(float2*)&g_att[((size_t)(b * SEQ + n + 8)) * EMB + col] = r1;
        }
    }
}

// ---------------------------------------------------------------------------
// Per-row inverse RMS (warp per row)
// ---------------------------------------------------------------------------
__global__ void rms_kernel()
{
    const int lane = threadIdx.x & 31, warp = threadIdx.x >> 5;
    const int row = blockIdx.x * 8 + warp;
    const float* p = g_att + (size_t)row * EMB;
    float ss = 0.f;
    #pragma unroll
    for (int i = 0; i < 6; i++) {
        float4 v = *(const float4*)(p + lane * 4 + i * 128);
        ss += v.x * v.x + v.y * v.y + v.z * v.z + v.w * v.w;
    }
    #pragma unroll
    for (int off = 16; off > 0; off >>= 1)
        ss += __shfl_xor_sync(0xffffffffu, ss, off);
    if (lane == 0) g_rms[row] = rsqrtf(ss * (1.0f / EMB) + 1e-6f);
}

// ---------------------------------------------------------------------------
// Output projection with fused RMSNorm: out = (att*rms*nw) @ Wp + bias
// 64x128 tile, 128 threads (4 warps, 16 rows each) -> higher occupancy.
// ---------------------------------------------------------------------------
__global__ __launch_bounds__(128) void proj_mma_kernel(const float* __restrict__ W,
                                                       const float* __restrict__ bias,
                                                       const float* __restrict__ nw,
                                                       float* __restrict__ out)
{
    __shared__ uint32_t As[64*36];
    __shared__ uint32_t Bs[32*136];

    const int tid  = threadIdx.x;
    const int lane = tid & 31, warp = tid >> 5;
    const int g = lane >> 2, tig = lane & 3;
    const int m0 = blockIdx.y * 64, n0 = blockIdx.x * 128;
    const int r = 16 * warp;

    float acc[16][4] = {};
    float rmsr[4];
    #pragma unroll
    for (int it = 0; it < 4; it++)
        rmsr[it] = g_rms[m0 + ((tid + it * 128) >> 3)];

    float4 ra[4], rn[4], rb[8];
    #pragma unroll
    for (int it = 0; it < 4; it++) {
        int i = tid + it * 128;
        int rowA = i >> 3, cA = i & 7;
        ra[it] = *(const float4*)(g_att + (size_t)(m0 + rowA) * EMB + 4 * cA);
        rn[it] = *(const float4*)(nw + 4 * cA);
    }
    #pragma unroll
    for (int it = 0; it < 8; it++) {
        int i = tid + it * 128;
        int rowB = i >> 5, cB = i & 31;
        rb[it] = *(const float4*)(W + (size_t)rowB * EMB + n0 + 4 * cB);
    }

    for (int kk = 0; kk < EMB; kk += 32) {
        #pragma unroll
        for (int it = 0; it < 4; it++) {
            int i = tid + it * 128;
            int rowA = i >> 3, cA = i & 7;
            uint32_t* d = &As[rowA * 36 + 4 * cA];
            d[0] = cvt_tf32(ra[it].x * rmsr[it] * rn[it].x);
            d[1] = cvt_tf32(ra[it].y * rmsr[it] * rn[it].y);
            d[2] = cvt_tf32(ra[it].z * rmsr[it] * rn[it].z);
            d[3] = cvt_tf32(ra[it].w * rmsr[it] * rn[it].w);
        }
        #pragma unroll
        for (int it = 0; it < 8; it++) {
            int i = tid + it * 128;
            int rowB = i >> 5, cB = i & 31;
            uint32_t* e = &Bs[rowB * 136 + 4 * cB];
            e[0] = cvt_tf32(rb[it].x); e[1] = cvt_tf32(rb[it].y);
            e[2] = cvt_tf32(rb[it].z); e[3] = cvt_tf32(rb[it].w);
        }
        __syncthreads();

        if (kk + 32 < EMB) {
            #pragma unroll
            for (int it = 0; it < 4; it++) {
                int i = tid + it * 128;
                int rowA = i >> 3, cA = i & 7;
                ra[it] = *(const float4*)(g_att + (size_t)(m0 + rowA) * EMB + kk + 32 + 4 * cA);
                rn[it] = *(const float4*)(nw + kk + 32 + 4 * cA);
            }
            #pragma unroll
            for (int it = 0; it < 8; it++) {
                int i = tid + it * 128;
                int rowB = i >> 5, cB = i & 31;
                rb[it] = *(const float4*)(W + (size_t)(kk + 32 + rowB) * EMB + n0 + 4 * cB);
            }
        }

        #pragma unroll
        for (int ks = 0; ks < 4; ks++) {
            uint32_t a[4];
            a[0] = As[(r + g)     * 36 + 8 * ks + tig];
            a[1] = As[(r + g + 8) * 36 + 8 * ks + tig];
            a[2] = As[(r + g)     * 36 + 8 * ks + tig + 4];
            a[3] = As[(r + g + 8) * 36 + 8 * ks + tig + 4];
            #pragma unroll
            for (int t = 0; t < 16; t++) {
                uint32_t b[2];
                b[0] = Bs[(8 * ks + tig)     * 136 + 8 * t + g];
                b[1] = Bs[(8 * ks + tig + 4) * 136 + 8 * t + g];
                mma8(acc[t], a, b);
            }
        }
        __syncthreads();
    }

    const int row0 = m0 + r + g;
    #pragma unroll
    for (int t = 0; t < 16; t++) {
        int c = n0 + 8 * t + 2 * tig;
        float2 r0 = make_float2(acc[t][0] + bias[c], acc[t][1] + bias[c + 1]);
        float2 r1 = make_float2(acc[t][2] + bias[c], acc[t][3] + bias[c + 1]);
        *(float2*)&out[(size_t)row0 * EMB + c]       = r0;
        *(float2*)&out[(size_t)(row0 + 8) * EMB + c] = r1;
    }
}

extern "C" void kernel_launch(void* const* d_in, const int* in_sizes, int n_in,
                              void* d_out, int out_size)
{
    const float* x  = (const float*)d_in[0];
    const float* W1 = (const float*)d_in[1];
    const float* W2 = (const float*)d_in[2];
    const float* Wp = (const float*)d_in[3];
    const float* bp = (const float*)d_in[4];
    const float* nw = (const float*)d_in[5];
    const float* l1 = (const float*)d_in[6];
    const float* l2 = (const float*)d_in[7];
    // d_in[8] = xpos (int64) unused: attention is non-causal in the reference
    float* out = (float*)d_out;

    qkv_mma_kernel<<<dim3(30, 32), 256>>>(x, W1, W2);

    const size_t smem = 57856u * 4;   // 231424 B
    cudaFuncSetAttribute(diff_attn_mma, cudaFuncAttributeMaxDynamicSharedMemorySize, (int)smem);
    diff_attn_mma<<<dim3(SEQ / 128, BSZ * NH), 512, smem>>>(l1, l2);

    rms_kernel<<<ROWS / 8, 256>>>();
    proj_mma_kernel<<<dim3(EMB / 128, ROWS / 64), 128>>>(Wp, bp, nw, out);
}

// round 6
// speedup vs baseline: 7.2945x; 1.4334x over previous
#include <cuda_runtime.h>
#include <cuda_fp16.h>
#include <math.h>
#include <stdint.h>

#define BSZ 2
#define SEQ 2048
#define EMB 768
#define NH 12
#define HDIM 64
#define ROWS (BSZ*SEQ)

// Scratch (allocation-free rule: __device__ globals). Q/K fp16 [B*H][seq][d]; V fp16 transposed [B*H][d][seq].
__device__ __half g_q1h[BSZ*NH*SEQ*HDIM];
__device__ __half g_k1h[BSZ*NH*SEQ*HDIM];
__device__ __half g_vth[BSZ*NH*SEQ*HDIM];
__device__ __half g_q2h[BSZ*NH*SEQ*HDIM];
__device__ __half g_k2h[BSZ*NH*SEQ*HDIM];
__device__ float g_att[ROWS*EMB];
__device__ float g_rms[ROWS];

// ---------------------------------------------------------------------------
// helpers
// ---------------------------------------------------------------------------
__device__ __forceinline__ uint32_t cvt_tf32(float x) {
    uint32_t u;
    asm("cvt.rna.tf32.f32 %0, %1;" : "=r"(u) : "f"(x));
    return u;
}
__device__ __forceinline__ float ex2f(float x) {
    float y;
    asm("ex2.approx.f32 %0, %1;" : "=f"(y) : "f"(x));
    return y;
}
__device__ __forceinline__ void mma8(float* c, const uint32_t* a, const uint32_t* b) {
    asm volatile(
        "mma.sync.aligned.m16n8k8.row.col.f32.tf32.tf32.f32 "
        "{%0,%1,%2,%3},{%4,%5,%6,%7},{%8,%9},{%0,%1,%2,%3};"
        : "+f"(c[0]), "+f"(c[1]), "+f"(c[2]), "+f"(c[3])
        : "r"(a[0]), "r"(a[1]), "r"(a[2]), "r"(a[3]), "r"(b[0]), "r"(b[1]));
}
__device__ __forceinline__ void mma16(float* c, const uint32_t* a, uint32_t b0, uint32_t b1) {
    asm volatile(
        "mma.sync.aligned.m16n8k16.row.col.f32.f16.f16.f32 "
        "{%0,%1,%2,%3},{%4,%5,%6,%7},{%8,%9},{%0,%1,%2,%3};"
        : "+f"(c[0]), "+f"(c[1]), "+f"(c[2]), "+f"(c[3])
        : "r"(a[0]), "r"(a[1]), "r"(a[2]), "r"(a[3]), "r"(b0), "r"(b1));
}
__device__ __forceinline__ uint32_t pack_h2(float lo, float hi) {
    __half2 h = __float22half2_rn(make_float2(lo, hi));
    return *(uint32_t*)&h;
}
#define CP16(dst_u32, src_ptr) \
    asm volatile("cp.async.cg.shared.global [%0], [%1], 16;" :: "r"(dst_u32), "l"(src_ptr))
#define CPCOMMIT() asm volatile("cp.async.commit_group;")

// 0.125 * log2(e): fold head-dim scale AND exp->exp2 conversion into Q
#define QSCALE 0.18033688011112042f

// ---------------------------------------------------------------------------
// Merged QKV projection GEMM (tf32 mma compute, fp16 output).
// grid (30, 32): bx<18 -> W1, bx>=18 -> W2 (first 1536 cols; v2 dead).
// V is written TRANSPOSED ([d][seq]) for fp16 PV B-fragments.
// ---------------------------------------------------------------------------
__global__ __launch_bounds__(256) void qkv_mma_kernel(const float* __restrict__ X,
                                                      const float* __restrict__ W1,
                                                      const float* __restrict__ W2)
{
    __shared__ uint32_t As[128*36];
    __shared__ uint32_t Bs[32*136];

    const int tid  = threadIdx.x;
    const int lane = tid & 31, warp = tid >> 5;
    const int g = lane >> 2, tig = lane & 3;
    const int wm = warp >> 1, wn = warp & 1;
    const int m0 = blockIdx.y * 128;
    const bool second = blockIdx.x >= 18;
    const float* __restrict__ W = second ? W2 : W1;
    const int n0 = (second ? blockIdx.x - 18 : blockIdx.x) * 128;

    float acc[2][8][4] = {};
    float4 ra[4], rb[4];

    #pragma unroll
    for (int it = 0; it < 4; it++) {
        int i = tid + it * 256;
        int rowA = i >> 3, cA = i & 7;
        ra[it] = *(const float4*)(X + (size_t)(m0 + rowA) * EMB + 4 * cA);
        int rowB = i >> 5, cB = i & 31;
        rb[it] = *(const float4*)(W + (size_t)rowB * 2304 + n0 + 4 * cB);
    }

    for (int kk = 0; kk < EMB; kk += 32) {
        #pragma unroll
        for (int it = 0; it < 4; it++) {
            int i = tid + it * 256;
            int rowA = i >> 3, cA = i & 7;
            uint32_t* d = &As[rowA * 36 + 4 * cA];
            d[0] = cvt_tf32(ra[it].x); d[1] = cvt_tf32(ra[it].y);
            d[2] = cvt_tf32(ra[it].z); d[3] = cvt_tf32(ra[it].w);
            int rowB = i >> 5, cB = i & 31;
            uint32_t* e = &Bs[rowB * 136 + 4 * cB];
            e[0] = cvt_tf32(rb[it].x); e[1] = cvt_tf32(rb[it].y);
            e[2] = cvt_tf32(rb[it].z); e[3] = cvt_tf32(rb[it].w);
        }
        __syncthreads();

        if (kk + 32 < EMB) {
            #pragma unroll
            for (int it = 0; it < 4; it++) {
                int i = tid + it * 256;
                int rowA = i >> 3, cA = i & 7;
                ra[it] = *(const float4*)(X + (size_t)(m0 + rowA) * EMB + kk + 32 + 4 * cA);
                int rowB = i >> 5, cB = i & 31;
                rb[it] = *(const float4*)(W + (size_t)(kk + 32 + rowB) * 2304 + n0 + 4 * cB);
            }
        }

        #pragma unroll
        for (int ks = 0; ks < 4; ks++) {
            uint32_t a[2][4], b[8][2];
            #pragma unroll
            for (int mt = 0; mt < 2; mt++) {
                int r = 32 * wm + 16 * mt;
                a[mt][0] = As[(r + g)     * 36 + 8 * ks + tig];
                a[mt][1] = As[(r + g + 8) * 36 + 8 * ks + tig];
                a[mt][2] = As[(r + g)     * 36 + 8 * ks + tig + 4];
                a[mt][3] = As[(r + g + 8) * 36 + 8 * ks + tig + 4];
            }
            #pragma unroll
            for (int t = 0; t < 8; t++) {
                b[t][0] = Bs[(8 * ks + tig)     * 136 + 64 * wn + 8 * t + g];
                b[t][1] = Bs[(8 * ks + tig + 4) * 136 + 64 * wn + 8 * t + g];
            }
            #pragma unroll
            for (int mt = 0; mt < 2; mt++)
                #pragma unroll
                for (int t = 0; t < 8; t++)
                    mma8(acc[mt][t], a[mt], b[t]);
        }
        __syncthreads();
    }

    const int cbase = n0 + 64 * wn;
    const int sel = cbase / EMB;
    const int h = (cbase - sel * EMB) >> 6;
    const int bb = m0 >> 11;

    if (!second && sel == 2) {
        // V -> transposed fp16 [d][seq]
        __half* vt = g_vth + (size_t)(bb * NH + h) * HDIM * SEQ;
        #pragma unroll
        for (int mt = 0; mt < 2; mt++) {
            int n = (m0 + 32 * wm + 16 * mt + g) & (SEQ - 1);
            #pragma unroll
            for (int t = 0; t < 8; t++) {
                int d0 = 8 * t + 2 * tig;
                vt[(size_t)d0 * SEQ + n]           = __float2half_rn(acc[mt][t][0]);
                vt[(size_t)(d0 + 1) * SEQ + n]     = __float2half_rn(acc[mt][t][1]);
                vt[(size_t)d0 * SEQ + n + 8]       = __float2half_rn(acc[mt][t][2]);
                vt[(size_t)(d0 + 1) * SEQ + n + 8] = __float2half_rn(acc[mt][t][3]);
            }
        }
    } else {
        __half* dst = second ? (sel == 0 ? g_q2h : g_k2h)
                             : (sel == 0 ? g_q1h : g_k1h);
        const float scl = (sel == 0) ? QSCALE : 1.0f;
        #pragma unroll
        for (int mt = 0; mt < 2; mt++) {
            int r = m0 + 32 * wm + 16 * mt + g;
            int n = r & (SEQ - 1);
            size_t base = (size_t)(bb * NH + h) * SEQ;
            #pragma unroll
            for (int t = 0; t < 8; t++) {
                int d0 = 8 * t + 2 * tig;
                *(uint32_t*)&dst[(base + n) * HDIM + d0] =
                    pack_h2(acc[mt][t][0] * scl, acc[mt][t][1] * scl);
                *(uint32_t*)&dst[(base + n + 8) * HDIM + d0] =
                    pack_h2(acc[mt][t][2] * scl, acc[mt][t][3] * scl);
            }
        }
    }
}

// ---------------------------------------------------------------------------
// Differential flash attention, fp16 m16n8k16 mma, 512 threads (16 warps).
// warp (qg = warp&7, kh = warp>>3): 16 q-rows x 32 k-cols. No online max
// (log2-scores bounded); l/O partials reduced once at the end.
// smem word offsets: Q2s 0 (128x36), K1s 4608 (2x64x36), K2s 9216,
// Vts 13824 (64x36), P1s 16128 (2kh x 128x20), P2s 21248. Total 26368 w.
// ---------------------------------------------------------------------------
__global__ __launch_bounds__(512) void diff_attn_fp16(const float* __restrict__ lam1,
                                                      const float* __restrict__ lam2)
{
    extern __shared__ uint32_t sm[];
    const int Q2O = 0, K1O = 4608, K2O = 9216, VO = 13824, P1O = 16128, P2O = 21248;

    const int tid  = threadIdx.x;
    const int lane = tid & 31, warp = tid >> 5;
    const int g = lane >> 2, tig = lane & 3;
    const int qg = warp & 7, kh = warp >> 3;
    const int r = 16 * qg;
    const int pb = kh * 2560;           // kh-private P region (words)
    const int bh = blockIdx.y;
    const int b = bh / NH, h = bh - b * NH;
    const int q0 = blockIdx.x * 128;

    const __half* Q1g = g_q1h + ((size_t)bh * SEQ + q0) * HDIM;
    const __half* Q2g = g_q2h + ((size_t)bh * SEQ + q0) * HDIM;
    const __half* K1g = g_k1h + (size_t)bh * SEQ * HDIM;
    const __half* K2g = g_k2h + (size_t)bh * SEQ * HDIM;
    const __half* Vtg = g_vth + (size_t)bh * HDIM * SEQ;

    // Q2 tile -> smem (128 rows x 64 halfs, stride 36 words)
    #pragma unroll
    for (int it = 0; it < 2; it++) {
        int i = tid + it * 512;
        int row = i >> 3, c8 = i & 7;
        *(uint4*)&sm[Q2O + row * 36 + c8 * 4] = *(const uint4*)(Q2g + row * 64 + c8 * 8);
    }
    // Q1 fragments -> registers (4 k-steps x 4 regs)
    uint32_t q1f[4][4];
    #pragma unroll
    for (int s = 0; s < 4; s++) {
        q1f[s][0] = *(const uint32_t*)(Q1g + (r + g)     * 64 + 16 * s + 2 * tig);
        q1f[s][1] = *(const uint32_t*)(Q1g + (r + g + 8) * 64 + 16 * s + 2 * tig);
        q1f[s][2] = *(const uint32_t*)(Q1g + (r + g)     * 64 + 16 * s + 2 * tig + 8);
        q1f[s][3] = *(const uint32_t*)(Q1g + (r + g + 8) * 64 + 16 * s + 2 * tig + 8);
    }

    const uint32_t smb = (uint32_t)__cvta_generic_to_shared(sm);

    auto prefetch_K = [&](int kt, int buf) {
        int row = tid >> 3, c = tid & 7;     // 64 rows x 8 chunks of 16B
        CP16(smb + (uint32_t)(K1O + buf * 2304 + row * 36 + c * 4) * 4,
             K1g + (size_t)kt * 4096 + row * 64 + c * 8);
        CP16(smb + (uint32_t)(K2O + buf * 2304 + row * 36 + c * 4) * 4,
             K2g + (size_t)kt * 4096 + row * 64 + c * 8);
        CPCOMMIT();
    };
    auto prefetch_V = [&](int kt) {
        int row = tid >> 3, c = tid & 7;     // 64 d-rows x 8 chunks
        CP16(smb + (uint32_t)(VO + row * 36 + c * 4) * 4,
             Vtg + (size_t)row * SEQ + kt * 64 + c * 8);
        CPCOMMIT();
    };

    prefetch_K(0, 0);

    float o1[8][4] = {}, o2[8][4] = {};
    float l1[2] = {0.f, 0.f}, l2[2] = {0.f, 0.f};

    const int NT = SEQ / 64;
    for (int kt = 0; kt < NT; kt++) {
        const int cur = kt & 1;
        const bool more = (kt + 1 < NT);
        prefetch_V(kt);
        if (more) {
            prefetch_K(kt + 1, cur ^ 1);
            asm volatile("cp.async.wait_group 2;");
        } else {
            asm volatile("cp.async.wait_group 1;");
        }
        __syncthreads();

        const int K1c = K1O + cur * 2304;
        const int K2c = K2O + cur * 2304;

        // ---- attn1: S1 = Q1 K1^T (Q1 from regs) ----
        {
            float s1[4][4] = {};
            #pragma unroll
            for (int s = 0; s < 4; s++) {
                #pragma unroll
                for (int t = 0; t < 4; t++) {
                    int kr = 32 * kh + 8 * t + g;
                    uint32_t b0 = sm[K1c + kr * 36 + 8 * s + tig];
                    uint32_t b1 = sm[K1c + kr * 36 + 8 * s + tig + 4];
                    mma16(s1[t], q1f[s], b0, b1);
                }
            }
            #pragma unroll
            for (int rr = 0; rr < 2; rr++) {
                float rs = 0.f;
                const int row = r + g + 8 * rr;
                #pragma unroll
                for (int t = 0; t < 4; t++) {
                    float p0 = ex2f(s1[t][2 * rr]);
                    float p1 = ex2f(s1[t][2 * rr + 1]);
                    rs += p0 + p1;
                    sm[P1O + pb + row * 20 + 4 * t + tig] = pack_h2(p0, p1);
                }
                l1[rr] += rs;
            }
        }
        // ---- attn2: S2 = Q2 K2^T (Q2 frags from smem) ----
        {
            float s2[4][4] = {};
            #pragma unroll
            for (int s = 0; s < 4; s++) {
                uint32_t aq[4];
                aq[0] = sm[Q2O + (r + g)     * 36 + 8 * s + tig];
                aq[1] = sm[Q2O + (r + g + 8) * 36 + 8 * s + tig];
                aq[2] = sm[Q2O + (r + g)     * 36 + 8 * s + tig + 4];
                aq[3] = sm[Q2O + (r + g + 8) * 36 + 8 * s + tig + 4];
                #pragma unroll
                for (int t = 0; t < 4; t++) {
                    int kr = 32 * kh + 8 * t + g;
                    uint32_t b0 = sm[K2c + kr * 36 + 8 * s + tig];
                    uint32_t b1 = sm[K2c + kr * 36 + 8 * s + tig + 4];
                    mma16(s2[t], aq, b0, b1);
                }
            }
            #pragma unroll
            for (int rr = 0; rr < 2; rr++) {
                float rs = 0.f;
                const int row = r + g + 8 * rr;
                #pragma unroll
                for (int t = 0; t < 4; t++) {
                    float p0 = ex2f(s2[t][2 * rr]);
                    float p1 = ex2f(s2[t][2 * rr + 1]);
                    rs += p0 + p1;
                    sm[P2O + pb + row * 20 + 4 * t + tig] = pack_h2(p0, p1);
                }
                l2[rr] += rs;
            }
        }
        __syncwarp();

        if (more) {
            asm volatile("cp.async.wait_group 1;");
        } else {
            asm volatile("cp.async.wait_group 0;");
        }
        __syncthreads();

        // ---- partial O += P(own 32 k-cols) @ V (Vt fragments shared) ----
        #pragma unroll
        for (int s2 = 0; s2 < 2; s2++) {
            uint32_t a1[4], a2[4];
            a1[0] = sm[P1O + pb + (r + g)     * 20 + 8 * s2 + tig];
            a1[1] = sm[P1O + pb + (r + g + 8) * 20 + 8 * s2 + tig];
            a1[2] = sm[P1O + pb + (r + g)     * 20 + 8 * s2 + tig + 4];
            a1[3] = sm[P1O + pb + (r + g + 8) * 20 + 8 * s2 + tig + 4];
            a2[0] = sm[P2O + pb + (r + g)     * 20 + 8 * s2 + tig];
            a2[1] = sm[P2O + pb + (r + g + 8) * 20 + 8 * s2 + tig];
            a2[2] = sm[P2O + pb + (r + g)     * 20 + 8 * s2 + tig + 4];
            a2[3] = sm[P2O + pb + (r + g + 8) * 20 + 8 * s2 + tig + 4];
            #pragma unroll
            for (int t = 0; t < 8; t++) {
                int vr = 8 * t + g;
                uint32_t b0 = sm[VO + vr * 36 + 16 * kh + 8 * s2 + tig];
                uint32_t b1 = sm[VO + vr * 36 + 16 * kh + 8 * s2 + tig + 4];
                mma16(o1[t], a1, b0, b1);
                mma16(o2[t], a2, b0, b1);
            }
        }
        __syncthreads();
    }

    // ---- final reduction across tig lanes (l) and kh warp pairs (l, O) ----
    #pragma unroll
    for (int rr = 0; rr < 2; rr++) {
        l1[rr] += __shfl_xor_sync(0xffffffffu, l1[rr], 1);
        l1[rr] += __shfl_xor_sync(0xffffffffu, l1[rr], 2);
        l2[rr] += __shfl_xor_sync(0xffffffffu, l2[rr], 1);
        l2[rr] += __shfl_xor_sync(0xffffffffu, l2[rr], 2);
    }
    float* ob1 = (float*)sm;            // 128x68 f32
    float* ob2 = (float*)(sm + 8704);
    float* lbuf = (float*)(sm + 17408); // 256 f32
    if (kh == 1) {
        #pragma unroll
        for (int t = 0; t < 8; t++) {
            *(float2*)&ob1[(r + g)     * 68 + 8 * t + 2 * tig] = make_float2(o1[t][0], o1[t][1]);
            *(float2*)&ob1[(r + g + 8) * 68 + 8 * t + 2 * tig] = make_float2(o1[t][2], o1[t][3]);
            *(float2*)&ob2[(r + g)     * 68 + 8 * t + 2 * tig] = make_float2(o2[t][0], o2[t][1]);
            *(float2*)&ob2[(r + g + 8) * 68 + 8 * t + 2 * tig] = make_float2(o2[t][2], o2[t][3]);
        }
        if (tig == 0) {
            lbuf[r + g]           = l1[0];
            lbuf[r + g + 8]       = l1[1];
            lbuf[128 + r + g]     = l2[0];
            lbuf[128 + r + g + 8] = l2[1];
        }
    }
    __syncthreads();
    if (kh == 0) {
        const float lam = lam1[h] - lam2[h] + 0.1f;
        const float i10 = 1.f / (l1[0] + lbuf[r + g]);
        const float i11 = 1.f / (l1[1] + lbuf[r + g + 8]);
        const float i20 = 1.f / (l2[0] + lbuf[128 + r + g]);
        const float i21 = 1.f / (l2[1] + lbuf[128 + r + g + 8]);
        const int n = q0 + r + g;
        #pragma unroll
        for (int t = 0; t < 8; t++) {
            const int col = h * HDIM + 8 * t + 2 * tig;
            float2 p10 = *(float2*)&ob1[(r + g)     * 68 + 8 * t + 2 * tig];
            float2 p11 = *(float2*)&ob1[(r + g + 8) * 68 + 8 * t + 2 * tig];
            float2 p20 = *(float2*)&ob2[(r + g)     * 68 + 8 * t + 2 * tig];
            float2 p21 = *(float2*)&ob2[(r + g + 8) * 68 + 8 * t + 2 * tig];
            float2 r0 = make_float2((o1[t][0] + p10.x) * i10 - lam * (o2[t][0] + p20.x) * i20,
                                    (o1[t][1] + p10.y) * i10 - lam * (o2[t][1] + p20.y) * i20);
            float2 r1 = make_float2((o1[t][2] + p11.x) * i11 - lam * (o2[t][2] + p21.x) * i21,
                                    (o1[t][3] + p11.y) * i11 - lam * (o2[t][3] + p21.y) * i21);
            *(float2*)&g_att[((size_t)(b * SEQ + n)) * EMB + col]     = r0;
            *(float2*)&g_att[((size_t)(b * SEQ + n + 8)) * EMB + col] = r1;
        }
    }
}

// ---------------------------------------------------------------------------
// Per-row inverse RMS (warp per row)
// ---------------------------------------------------------------------------
__global__ void rms_kernel()
{
    const int lane = threadIdx.x & 31, warp = threadIdx.x >> 5;
    const int row = blockIdx.x * 8 + warp;
    const float* p = g_att + (size_t)row * EMB;
    float ss = 0.f;
    #pragma unroll
    for (int i = 0; i < 6; i++) {
        float4 v = *(const float4*)(p + lane * 4 + i * 128);
        ss += v.x * v.x + v.y * v.y + v.z * v.z + v.w * v.w;
    }
    #pragma unroll
    for (int off = 16; off > 0; off >>= 1)
        ss += __shfl_xor_sync(0xffffffffu, ss, off);
    if (lane == 0) g_rms[row] = rsqrtf(ss * (1.0f / EMB) + 1e-6f);
}

// ---------------------------------------------------------------------------
// Output projection with fused RMSNorm: out = (att*rms*nw) @ Wp + bias
// ---------------------------------------------------------------------------
__global__ __launch_bounds__(128) void proj_mma_kernel(const float* __restrict__ W,
                                                       const float* __restrict__ bias,
                                                       const float* __restrict__ nw,
                                                       float* __restrict__ out)
{
    __shared__ uint32_t As[64*36];
    __shared__ uint32_t Bs[32*136];

    const int tid  = threadIdx.x;
    const int lane = tid & 31, warp = tid >> 5;
    const int g = lane >> 2, tig = lane & 3;
    const int m0 = blockIdx.y * 64, n0 = blockIdx.x * 128;
    const int r = 16 * warp;

    float acc[16][4] = {};
    float rmsr[4];
    #pragma unroll
    for (int it = 0; it < 4; it++)
        rmsr[it] = g_rms[m0 + ((tid + it * 128) >> 3)];

    float4 ra[4], rn[4], rb[8];
    #pragma unroll
    for (int it = 0; it < 4; it++) {
        int i = tid + it * 128;
        int rowA = i >> 3, cA = i & 7;
        ra[it] = *(const float4*)(g_att + (size_t)(m0 + rowA) * EMB + 4 * cA);
        rn[it] = *(const float4*)(nw + 4 * cA);
    }
    #pragma unroll
    for (int it = 0; it < 8; it++) {
        int i = tid + it * 128;
        int rowB = i >> 5, cB = i & 31;
        rb[it] = *(const float4*)(W + (size_t)rowB * EMB + n0 + 4 * cB);
    }

    for (int kk = 0; kk < EMB; kk += 32) {
        #pragma unroll
        for (int it = 0; it < 4; it++) {
            int i = tid + it * 128;
            int rowA = i >> 3, cA = i & 7;
            uint32_t* d = &As[rowA * 36 + 4 * cA];
            d[0] = cvt_tf32(ra[it].x * rmsr[it] * rn[it].x);
            d[1] = cvt_tf32(ra[it].y * rmsr[it] * rn[it].y);
            d[2] = cvt_tf32(ra[it].z * rmsr[it] * rn[it].z);
            d[3] = cvt_tf32(ra[it].w * rmsr[it] * rn[it].w);
        }
        #pragma unroll
        for (int it = 0; it < 8; it++) {
            int i = tid + it * 128;
            int rowB = i >> 5, cB = i & 31;
            uint32_t* e = &Bs[rowB * 136 + 4 * cB];
            e[0] = cvt_tf32(rb[it].x); e[1] = cvt_tf32(rb[it].y);
            e[2] = cvt_tf32(rb[it].z); e[3] = cvt_tf32(rb[it].w);
        }
        __syncthreads();

        if (kk + 32 < EMB) {
            #pragma unroll
            for (int it = 0; it < 4; it++) {
                int i = tid + it * 128;
                int rowA = i >> 3, cA = i & 7;
                ra[it] = *(const float4*)(g_att + (size_t)(m0 + rowA) * EMB + kk + 32 + 4 * cA);
                rn[it] = *(const float4*)(nw + kk + 32 + 4 * cA);
            }
            #pragma unroll
            for (int it = 0; it < 8; it++) {
                int i = tid + it * 128;
                int rowB = i >> 5, cB = i & 31;
                rb[it] = *(const float4*)(W + (size_t)(kk + 32 + rowB) * EMB + n0 + 4 * cB);
            }
        }

        #pragma unroll
        for (int ks = 0; ks < 4; ks++) {
            uint32_t a[4];
            a[0] = As[(r + g)     * 36 + 8 * ks + tig];
            a[1] = As[(r + g + 8) * 36 + 8 * ks + tig];
            a[2] = As[(r + g)     * 36 + 8 * ks + tig + 4];
            a[3] = As[(r + g + 8) * 36 + 8 * ks + tig + 4];
            #pragma unroll
            for (int t = 0; t < 16; t++) {
                uint32_t b[2];
                b[0] = Bs[(8 * ks + tig)     * 136 + 8 * t + g];
                b[1] = Bs[(8 * ks + tig + 4) * 136 + 8 * t + g];
                mma8(acc[t], a, b);
            }
        }
        __syncthreads();
    }

    const int row0 = m0 + r + g;
    #pragma unroll
    for (int t = 0; t < 16; t++) {
        int c = n0 + 8 * t + 2 * tig;
        float2 r0 = make_float2(acc[t][0] + bias[c], acc[t][1] + bias[c + 1]);
        float2 r1 = make_float2(acc[t][2] + bias[c], acc[t][3] + bias[c + 1]);
        *(float2*)&out[(size_t)row0 * EMB + c]       = r0;
        *(float2*)&out[(size_t)(row0 + 8) * EMB + c] = r1;
    }
}

extern "C" void kernel_launch(void* const* d_in, const int* in_sizes, int n_in,
                              void* d_out, int out_size)
{
    const float* x  = (const float*)d_in[0];
    const float* W1 = (const float*)d_in[1];
    const float* W2 = (const float*)d_in[2];
    const float* Wp = (const float*)d_in[3];
    const float* bp = (const float*)d_in[4];
    const float* nw = (const float*)d_in[5];
    const float* l1 = (const float*)d_in[6];
    const float* l2 = (const float*)d_in[7];
    // d_in[8] = xpos (int64) unused: attention is non-causal in the reference
    float* out = (float*)d_out;

    qkv_mma_kernel<<<dim3(30, 32), 256>>>(x, W1, W2);

    const size_t smem = 26368u * 4;   // 105472 B
    cudaFuncSetAttribute(diff_attn_fp16, cudaFuncAttributeMaxDynamicSharedMemorySize, (int)smem);
    diff_attn_fp16<<<dim3(SEQ / 128, BSZ * NH), 512, smem>>>(l1, l2);

    rms_kernel<<<ROWS / 8, 256>>>();
    proj_mma_kernel<<<dim3(EMB / 128, ROWS / 64), 128>>>(Wp, bp, nw, out);
}

// round 7
// speedup vs baseline: 8.4800x; 1.1625x over previous
#include <cuda_runtime.h>
#include <cuda_fp16.h>
#include <math.h>
#include <stdint.h>

#define BSZ 2
#define SEQ 2048
#define EMB 768
#define NH 12
#define HDIM 64
#define ROWS (BSZ*SEQ)

// Q/K fp16 [B*H][seq][d-permuted]; V fp16 transposed [B*H][d][seq-permuted].
// Permutation within each 16-group: logical (2i,2i+1,2i+8,2i+9) stored at phys 4i..4i+3.
__device__ __half g_q1h[BSZ*NH*SEQ*HDIM];
__device__ __half g_k1h[BSZ*NH*SEQ*HDIM];
__device__ __half g_vth[BSZ*NH*SEQ*HDIM];
__device__ __half g_q2h[BSZ*NH*SEQ*HDIM];
__device__ __half g_k2h[BSZ*NH*SEQ*HDIM];
__device__ float g_att[ROWS*EMB];
__device__ float g_rms[ROWS];

// ---------------------------------------------------------------------------
__device__ __forceinline__ float ex2f(float x) {
    float y;
    asm("ex2.approx.f32 %0, %1;" : "=f"(y) : "f"(x));
    return y;
}
__device__ __forceinline__ void mma16(float* c, const uint32_t* a, uint32_t b0, uint32_t b1) {
    asm volatile(
        "mma.sync.aligned.m16n8k16.row.col.f32.f16.f16.f32 "
        "{%0,%1,%2,%3},{%4,%5,%6,%7},{%8,%9},{%0,%1,%2,%3};"
        : "+f"(c[0]), "+f"(c[1]), "+f"(c[2]), "+f"(c[3])
        : "r"(a[0]), "r"(a[1]), "r"(a[2]), "r"(a[3]), "r"(b0), "r"(b1));
}
__device__ __forceinline__ uint32_t pack_h2(float lo, float hi) {
    __half2 h = __float22half2_rn(make_float2(lo, hi));
    return *(uint32_t*)&h;
}
#define CP16(dst_u32, src_ptr) \
    asm volatile("cp.async.cg.shared.global [%0], [%1], 16;" :: "r"(dst_u32), "l"(src_ptr))
#define CPCOMMIT() asm volatile("cp.async.commit_group;")

// 0.125 * log2(e): fold head-dim scale AND exp->exp2 conversion into Q
#define QSCALE 0.18033688011112042f

// ---------------------------------------------------------------------------
// Merged QKV projection GEMM, fp16 m16n8k16.
// grid (30, 32): bx<18 -> W1, bx>=18 -> W2 (first 1536 cols; v2 dead).
// Outputs fp16 with fragment permutation; V transposed [d][seq-perm].
// ---------------------------------------------------------------------------
__global__ __launch_bounds__(256) void qkv_mma_kernel(const float* __restrict__ X,
                                                      const float* __restrict__ W1,
                                                      const float* __restrict__ W2)
{
    __shared__ __half As[128*48];
    __shared__ __half Bs[128*48];

    const int tid  = threadIdx.x;
    const int lane = tid & 31, warp = tid >> 5;
    const int g = lane >> 2, tig = lane & 3;
    const int wm = warp >> 1, wn = warp & 1;
    const int m0 = blockIdx.y * 128;
    const bool second = blockIdx.x >= 18;
    const float* __restrict__ W = second ? W2 : W1;
    const int n0 = (second ? blockIdx.x - 18 : blockIdx.x) * 128;

    float acc[2][8][4] = {};

    for (int kk = 0; kk < EMB; kk += 32) {
        // A tile: X[m0..m0+127][kk..kk+31] -> fp16 permuted [row][k], stride 48
        #pragma unroll
        for (int it = 0; it < 4; it++) {
            int i = tid + it * 256;
            int rowA = i >> 3, c = i & 7;
            float4 v = *(const float4*)(X + (size_t)(m0 + rowA) * EMB + kk + 4 * c);
            int q = c & 3;
            int base = rowA * 48 + (c >> 2) * 16;
            int p1 = (q & 1) * 8 + (q >> 1) * 2;
            *(uint32_t*)&As[base + p1]     = pack_h2(v.x, v.y);
            *(uint32_t*)&As[base + p1 + 4] = pack_h2(v.z, v.w);
        }
        // B tile: W[kk..kk+31][n0..n0+127] -> transposed fp16 permuted [n][k], stride 48
        #pragma unroll
        for (int it = 0; it < 4; it++) {
            int i = tid + it * 256;
            int n = i & 127, kg = i >> 7;
            const float* wp = W + (size_t)(kk + 4 * kg) * 2304 + n0 + n;
            float w0 = wp[0], w1 = wp[2304], w2 = wp[2 * 2304], w3 = wp[3 * 2304];
            int q = kg & 3;
            int base = n * 48 + (kg >> 2) * 16;
            int p1 = (q & 1) * 8 + (q >> 1) * 2;
            *(uint32_t*)&Bs[base + p1]     = pack_h2(w0, w1);
            *(uint32_t*)&Bs[base + p1 + 4] = pack_h2(w2, w3);
        }
        __syncthreads();

        #pragma unroll
        for (int s = 0; s < 2; s++) {
            uint32_t a[2][4];
            #pragma unroll
            for (int mt = 0; mt < 2; mt++) {
                int row = 32 * wm + 16 * mt;
                uint2 u = *(uint2*)&As[(row + g)     * 48 + 16 * s + 4 * tig];
                uint2 v = *(uint2*)&As[(row + g + 8) * 48 + 16 * s + 4 * tig];
                a[mt][0] = u.x; a[mt][1] = v.x; a[mt][2] = u.y; a[mt][3] = v.y;
            }
            #pragma unroll
            for (int t = 0; t < 8; t++) {
                uint2 bb = *(uint2*)&Bs[(64 * wn + 8 * t + g) * 48 + 16 * s + 4 * tig];
                mma16(acc[0][t], a[0], bb.x, bb.y);
                mma16(acc[1][t], a[1], bb.x, bb.y);
            }
        }
        __syncthreads();
    }

    const int cbase = n0 + 64 * wn;
    const int sel = cbase / EMB;
    const int h = (cbase - sel * EMB) >> 6;
    const int bb = m0 >> 11;

    if (!second && sel == 2) {
        // V -> transposed fp16 [d][seq-permuted]
        __half* vt = g_vth + (size_t)(bb * NH + h) * HDIM * SEQ;
        #pragma unroll
        for (int mt = 0; mt < 2; mt++) {
            int rb = (m0 & (SEQ - 1)) + 32 * wm + 16 * mt;   // multiple of 16
            int n1p = rb + 4 * (g >> 1) + (g & 1);
            #pragma unroll
            for (int t = 0; t < 8; t++) {
                int d0 = 8 * t + 2 * tig;
                vt[(size_t)d0 * SEQ + n1p]           = __float2half_rn(acc[mt][t][0]);
                vt[(size_t)(d0 + 1) * SEQ + n1p]     = __float2half_rn(acc[mt][t][1]);
                vt[(size_t)d0 * SEQ + n1p + 2]       = __float2half_rn(acc[mt][t][2]);
                vt[(size_t)(d0 + 1) * SEQ + n1p + 2] = __float2half_rn(acc[mt][t][3]);
            }
        }
    } else {
        __half* dst = second ? (sel == 0 ? g_q2h : g_k2h)
                             : (sel == 0 ? g_q1h : g_k1h);
        const float scl = (sel == 0) ? QSCALE : 1.0f;
        #pragma unroll
        for (int mt = 0; mt < 2; mt++) {
            int n = (m0 + 32 * wm + 16 * mt + g) & (SEQ - 1);
            size_t base = (size_t)(bb * NH + h) * SEQ;
            #pragma unroll
            for (int t = 0; t < 8; t++) {
                int dphys = 16 * (t >> 1) + 4 * tig + 2 * (t & 1);
                *(uint32_t*)&dst[(base + n) * HDIM + dphys] =
                    pack_h2(acc[mt][t][0] * scl, acc[mt][t][1] * scl);
                *(uint32_t*)&dst[(base + n + 8) * HDIM + dphys] =
                    pack_h2(acc[mt][t][2] * scl, acc[mt][t][3] * scl);
            }
        }
    }
}

// ---------------------------------------------------------------------------
// Differential flash attention, fp16 mma, 512 threads (16 warps), k-split.
// warp (qg, kh): 16 q-rows x 32 k-cols. P stays in registers (S-accumulator
// layout == PV A-fragment layout). No online max; l/O reduced at the end.
// smem (halfs): Q2 0 (128x80), K1 10240 (2x64x80), K2 20480, V 30720 (64x80).
// ---------------------------------------------------------------------------
__global__ __launch_bounds__(512) void diff_attn_fp16(const float* __restrict__ lam1,
                                                      const float* __restrict__ lam2)
{
    extern __shared__ __align__(16) char smraw[];
    __half* smh = (__half*)smraw;
    const int Q2H = 0, K1H = 10240, K2H = 20480, VH = 30720;

    const int tid  = threadIdx.x;
    const int lane = tid & 31, warp = tid >> 5;
    const int g = lane >> 2, tig = lane & 3;
    const int qg = warp & 7, kh = warp >> 3;
    const int r = 16 * qg;
    const int bh = blockIdx.y;
    const int b = bh / NH, h = bh - b * NH;
    const int q0 = blockIdx.x * 128;

    const __half* Q1g = g_q1h + ((size_t)bh * SEQ + q0) * HDIM;
    const __half* Q2g = g_q2h + ((size_t)bh * SEQ + q0) * HDIM;
    const __half* K1g = g_k1h + (size_t)bh * SEQ * HDIM;
    const __half* K2g = g_k2h + (size_t)bh * SEQ * HDIM;
    const __half* Vtg = g_vth + (size_t)bh * HDIM * SEQ;

    // Q2 tile -> smem raw copy (perm preserved), stride 80 halfs
    #pragma unroll
    for (int it = 0; it < 2; it++) {
        int i = tid + it * 512;
        int row = i >> 3, c = i & 7;
        *(uint4*)&smh[Q2H + row * 80 + c * 8] = *(const uint4*)(Q2g + row * 64 + c * 8);
    }
    // Q1 fragments -> registers (LDG.64 thanks to permuted layout)
    uint32_t q1f[4][4];
    #pragma unroll
    for (int s = 0; s < 4; s++) {
        uint2 u = *(const uint2*)(Q1g + (r + g)     * 64 + 16 * s + 4 * tig);
        uint2 v = *(const uint2*)(Q1g + (r + g + 8) * 64 + 16 * s + 4 * tig);
        q1f[s][0] = u.x; q1f[s][1] = v.x; q1f[s][2] = u.y; q1f[s][3] = v.y;
    }

    const uint32_t smb = (uint32_t)__cvta_generic_to_shared(smraw);

    auto prefetch_K = [&](int kt, int buf) {
        int row = tid >> 3, c = tid & 7;
        CP16(smb + (uint32_t)(K1H + buf * 5120 + row * 80 + c * 8) * 2,
             K1g + (size_t)kt * 4096 + row * 64 + c * 8);
        CP16(smb + (uint32_t)(K2H + buf * 5120 + row * 80 + c * 8) * 2,
             K2g + (size_t)kt * 4096 + row * 64 + c * 8);
        CPCOMMIT();
    };
    auto prefetch_V = [&](int kt) {
        int row = tid >> 3, c = tid & 7;
        CP16(smb + (uint32_t)(VH + row * 80 + c * 8) * 2,
             Vtg + (size_t)row * SEQ + kt * 64 + c * 8);
        CPCOMMIT();
    };

    prefetch_K(0, 0);

    float o1[8][4] = {}, o2[8][4] = {};
    float l1[2] = {0.f, 0.f}, l2[2] = {0.f, 0.f};

    const int NT = SEQ / 64;
    for (int kt = 0; kt < NT; kt++) {
        const int cur = kt & 1;
        const bool more = (kt + 1 < NT);
        prefetch_V(kt);
        if (more) {
            prefetch_K(kt + 1, cur ^ 1);
            asm volatile("cp.async.wait_group 2;");
        } else {
            asm volatile("cp.async.wait_group 1;");
        }
        __syncthreads();

        const int K1c = K1H + cur * 5120;
        const int K2c = K2H + cur * 5120;

        uint32_t pa1[2][4], pa2[2][4];
        // ---- attn1: S1 = Q1 K1^T; exp -> PV A-fragments in registers ----
        {
            float s1[4][4] = {};
            #pragma unroll
            for (int s = 0; s < 4; s++) {
                #pragma unroll
                for (int t = 0; t < 4; t++) {
                    int kr = 32 * kh + 8 * t + g;
                    uint2 kb = *(uint2*)&smh[K1c + kr * 80 + 16 * s + 4 * tig];
                    mma16(s1[t], q1f[s], kb.x, kb.y);
                }
            }
            #pragma unroll
            for (int t = 0; t < 4; t++) {
                float p0 = ex2f(s1[t][0]);
                float p1 = ex2f(s1[t][1]);
                float p2 = ex2f(s1[t][2]);
                float p3 = ex2f(s1[t][3]);
                l1[0] += p0 + p1;
                l1[1] += p2 + p3;
                pa1[t >> 1][2 * (t & 1)]     = pack_h2(p0, p1);
                pa1[t >> 1][2 * (t & 1) + 1] = pack_h2(p2, p3);
            }
        }
        // ---- attn2: S2 = Q2 K2^T ----
        {
            float s2[4][4] = {};
            #pragma unroll
            for (int s = 0; s < 4; s++) {
                uint32_t aq[4];
                uint2 u = *(uint2*)&smh[Q2H + (r + g)     * 80 + 16 * s + 4 * tig];
                uint2 v = *(uint2*)&smh[Q2H + (r + g + 8) * 80 + 16 * s + 4 * tig];
                aq[0] = u.x; aq[1] = v.x; aq[2] = u.y; aq[3] = v.y;
                #pragma unroll
                for (int t = 0; t < 4; t++) {
                    int kr = 32 * kh + 8 * t + g;
                    uint2 kb = *(uint2*)&smh[K2c + kr * 80 + 16 * s + 4 * tig];
                    mma16(s2[t], aq, kb.x, kb.y);
                }
            }
            #pragma unroll
            for (int t = 0; t < 4; t++) {
                float p0 = ex2f(s2[t][0]);
                float p1 = ex2f(s2[t][1]);
                float p2 = ex2f(s2[t][2]);
                float p3 = ex2f(s2[t][3]);
                l2[0] += p0 + p1;
                l2[1] += p2 + p3;
                pa2[t >> 1][2 * (t & 1)]     = pack_h2(p0, p1);
                pa2[t >> 1][2 * (t & 1) + 1] = pack_h2(p2, p3);
            }
        }

        if (more) {
            asm volatile("cp.async.wait_group 1;");
        } else {
            asm volatile("cp.async.wait_group 0;");
        }
        __syncthreads();   // V visible to all threads

        // ---- O += P @ V (P in regs; V fragments shared between attns) ----
        #pragma unroll
        for (int s2 = 0; s2 < 2; s2++) {
            #pragma unroll
            for (int t = 0; t < 8; t++) {
                int vr = 8 * t + g;
                uint2 vb = *(uint2*)&smh[VH + vr * 80 + 32 * kh + 16 * s2 + 4 * tig];
                mma16(o1[t], pa1[s2], vb.x, vb.y);
                mma16(o2[t], pa2[s2], vb.x, vb.y);
            }
        }
        __syncthreads();   // protect K/V buffers before next prefetch
    }

    // ---- final reduction across tig lanes (l) and kh warp pairs (l, O) ----
    #pragma unroll
    for (int rr = 0; rr < 2; rr++) {
        l1[rr] += __shfl_xor_sync(0xffffffffu, l1[rr], 1);
        l1[rr] += __shfl_xor_sync(0xffffffffu, l1[rr], 2);
        l2[rr] += __shfl_xor_sync(0xffffffffu, l2[rr], 1);
        l2[rr] += __shfl_xor_sync(0xffffffffu, l2[rr], 2);
    }
    float* ob1 = (float*)smraw;          // 128x68 f32
    float* ob2 = ob1 + 8704;
    float* lbuf = ob2 + 8704;            // 256 f32 (total 70656 B <= 71680)
    if (kh == 1) {
        #pragma unroll
        for (int t = 0; t < 8; t++) {
            *(float2*)&ob1[(r + g)     * 68 + 8 * t + 2 * tig] = make_float2(o1[t][0], o1[t][1]);
            *(float2*)&ob1[(r + g + 8) * 68 + 8 * t + 2 * tig] = make_float2(o1[t][2], o1[t][3]);
            *(float2*)&ob2[(r + g)     * 68 + 8 * t + 2 * tig] = make_float2(o2[t][0], o2[t][1]);
            *(float2*)&ob2[(r + g + 8) * 68 + 8 * t + 2 * tig] = make_float2(o2[t][2], o2[t][3]);
        }
        if (tig == 0) {
            lbuf[r + g]           = l1[0];
            lbuf[r + g + 8]       = l1[1];
            lbuf[128 + r + g]     = l2[0];
            lbuf[128 + r + g + 8] = l2[1];
        }
    }
    __syncthreads();
    if (kh == 0) {
        const float lam = lam1[h] - lam2[h] + 0.1f;
        const float i10 = 1.f / (l1[0] + lbuf[r + g]);
        const float i11 = 1.f / (l1[1] + lbuf[r + g + 8]);
        const float i20 = 1.f / (l2[0] + lbuf[128 + r + g]);
        const float i21 = 1.f / (l2[1] + lbuf[128 + r + g + 8]);
        const int n = q0 + r + g;
        #pragma unroll
        for (int t = 0; t < 8; t++) {
            const int col = h * HDIM + 8 * t + 2 * tig;
            float2 p10 = *(float2*)&ob1[(r + g)     * 68 + 8 * t + 2 * tig];
            float2 p11 = *(float2*)&ob1[(r + g + 8) * 68 + 8 * t + 2 * tig];
            float2 p20 = *(float2*)&ob2[(r + g)     * 68 + 8 * t + 2 * tig];
            float2 p21 = *(float2*)&ob2[(r + g + 8) * 68 + 8 * t + 2 * tig];
            float2 r0 = make_float2((o1[t][0] + p10.x) * i10 - lam * (o2[t][0] + p20.x) * i20,
                                    (o1[t][1] + p10.y) * i10 - lam * (o2[t][1] + p20.y) * i20);
            float2 r1 = make_float2((o1[t][2] + p11.x) * i11 - lam * (o2[t][2] + p21.x) * i21,
                                    (o1[t][3] + p11.y) * i11 - lam * (o2[t][3] + p21.y) * i21);
            *(float2*)&g_att[((size_t)(b * SEQ + n)) * EMB + col]     = r0;
            *(float2*)&g_att[((size_t)(b * SEQ + n + 8)) * EMB + col] = r1;
        }
    }
}

// ---------------------------------------------------------------------------
// Per-row inverse RMS (warp per row)
// ---------------------------------------------------------------------------
__global__ void rms_kernel()
{
    const int lane = threadIdx.x & 31, warp = threadIdx.x >> 5;
    const int row = blockIdx.x * 8 + warp;
    const float* p = g_att + (size_t)row * EMB;
    float ss = 0.f;
    #pragma unroll
    for (int i = 0; i < 6; i++) {
        float4 v = *(const float4*)(p + lane * 4 + i * 128);
        ss += v.x * v.x + v.y * v.y + v.z * v.z + v.w * v.w;
    }
    #pragma unroll
    for (int off = 16; off > 0; off >>= 1)
        ss += __shfl_xor_sync(0xffffffffu, ss, off);
    if (lane == 0) g_rms[row] = rsqrtf(ss * (1.0f / EMB) + 1e-6f);
}

// ---------------------------------------------------------------------------
// Output projection with fused RMSNorm, fp16 mma: out = (att*rms*nw)@Wp + bias
// 64x128 tile, 128 threads (4 warps, 16 rows each).
// ---------------------------------------------------------------------------
__global__ __launch_bounds__(128) void proj_mma_kernel(const float* __restrict__ W,
                                                       const float* __restrict__ bias,
                                                       const float* __restrict__ nw,
                                                       float* __restrict__ out)
{
    __shared__ __half As[64*48];
    __shared__ __half Bs[128*48];

    const int tid  = threadIdx.x;
    const int lane = tid & 31, warp = tid >> 5;
    const int g = lane >> 2, tig = lane & 3;
    const int m0 = blockIdx.y * 64, n0 = blockIdx.x * 128;
    const int r = 16 * warp;

    float acc[16][4] = {};

    for (int kk = 0; kk < EMB; kk += 32) {
        // A: (att * rms * nw) fp16 permuted [row][k], stride 48
        #pragma unroll
        for (int it = 0; it < 4; it++) {
            int i = tid + it * 128;
            int rowA = i >> 3, c = i & 7;
            float rm = g_rms[m0 + rowA];
            float4 v = *(const float4*)(g_att + (size_t)(m0 + rowA) * EMB + kk + 4 * c);
            float4 w = *(const float4*)(nw + kk + 4 * c);
            int q = c & 3;
            int base = rowA * 48 + (c >> 2) * 16;
            int p1 = (q & 1) * 8 + (q >> 1) * 2;
            *(uint32_t*)&As[base + p1]     = pack_h2(v.x * rm * w.x, v.y * rm * w.y);
            *(uint32_t*)&As[base + p1 + 4] = pack_h2(v.z * rm * w.z, v.w * rm * w.w);
        }
        // B: Wp transposed fp16 permuted [n][k], stride 48
        #pragma unroll
        for (int it = 0; it < 8; it++) {
            int i = tid + it * 128;
            int n = i & 127, kg = i >> 7;
            const float* wp = W + (size_t)(kk + 4 * kg) * EMB + n0 + n;
            float w0 = wp[0], w1 = wp[EMB], w2 = wp[2 * EMB], w3 = wp[3 * EMB];
            int q = kg & 3;
            int base = n * 48 + (kg >> 2) * 16;
            int p1 = (q & 1) * 8 + (q >> 1) * 2;
            *(uint32_t*)&Bs[base + p1]     = pack_h2(w0, w1);
            *(uint32_t*)&Bs[base + p1 + 4] = pack_h2(w2, w3);
        }
        __syncthreads();

        #pragma unroll
        for (int s = 0; s < 2; s++) {
            uint32_t a[4];
            uint2 u = *(uint2*)&As[(r + g)     * 48 + 16 * s + 4 * tig];
            uint2 v = *(uint2*)&As[(r + g + 8) * 48 + 16 * s + 4 * tig];
            a[0] = u.x; a[1] = v.x; a[2] = u.y; a[3] = v.y;
            #pragma unroll
            for (int t = 0; t < 16; t++) {
                uint2 bb = *(uint2*)&Bs[(8 * t + g) * 48 + 16 * s + 4 * tig];
                mma16(acc[t], a, bb.x, bb.y);
            }
        }
        __syncthreads();
    }

    const int row0 = m0 + r + g;
    #pragma unroll
    for (int t = 0; t < 16; t++) {
        int c = n0 + 8 * t + 2 * tig;
        float2 r0 = make_float2(acc[t][0] + bias[c], acc[t][1] + bias[c + 1]);
        float2 r1 = make_float2(acc[t][2] + bias[c], acc[t][3] + bias[c + 1]);
        *(float2*)&out[(size_t)row0 * EMB + c]       = r0;
        *(float2*)&out[(size_t)(row0 + 8) * EMB + c] = r1;
    }
}

extern "C" void kernel_launch(void* const* d_in, const int* in_sizes, int n_in,
                              void* d_out, int out_size)
{
    const float* x  = (const float*)d_in[0];
    const float* W1 = (const float*)d_in[1];
    const float* W2 = (const float*)d_in[2];
    const float* Wp = (const float*)d_in[3];
    const float* bp = (const float*)d_in[4];
    const float* nw = (const float*)d_in[5];
    const float* l1 = (const float*)d_in[6];
    const float* l2 = (const float*)d_in[7];
    // d_in[8] = xpos (int64) unused: attention is non-causal in the reference
    float* out = (float*)d_out;

    qkv_mma_kernel<<<dim3(30, 32), 256>>>(x, W1, W2);

    const size_t smem = 35840u * 2;   // 71680 B
    cudaFuncSetAttribute(diff_attn_fp16, cudaFuncAttributeMaxDynamicSharedMemorySize, (int)smem);
    diff_attn_fp16<<<dim3(SEQ / 128, BSZ * NH), 512, smem>>>(l1, l2);

    rms_kernel<<<ROWS / 8, 256>>>();
    proj_mma_kernel<<<dim3(EMB / 128, ROWS / 64), 128>>>(Wp, bp, nw, out);
}